// round 8
// baseline (speedup 1.0000x reference)
#include <cuda_runtime.h>
#include <cuda_fp16.h>
#include <cstdint>

// Problem dims (fixed by the dataset)
#define Bb 4
#define Ss 4096
#define Tt (Bb*Ss)     // 16384 tokens
#define Hh 2048
#define Mm 8
#define PKk 32
#define NSn 16
#define Vv 128
#define KC (Vv+Hh)     // 2176

// ---------------------------------------------------------------------------
// Global scratch (static __device__ arrays; allocation-free)
// ---------------------------------------------------------------------------
__device__ __align__(16) __half g_Ahi[(size_t)Tt*KC];   // combined [mem|h] hi fp16
__device__ __align__(16) __half g_Alo[(size_t)Tt*KC];   // combined [mem|h] lo fp16
__device__ __align__(16) __half g_B2 [(size_t)Hh*KC];   // Wout^T fp16 [2048][2176]
__device__ __align__(16) __half g_Shi[(size_t)128*Hh];  // S = Wk^T @ sln, hi [128][2048]
__device__ __align__(16) __half g_Slo[(size_t)128*Hh];  // S lo

__device__ __forceinline__ void split2h(float v, __half& hi, __half& lo) {
    hi = __float2half(v);
    lo = __float2half(v - __half2float(hi));
}

__device__ __forceinline__ uint32_t smem_u32(const void* p) {
    uint32_t a;
    asm("{ .reg .u64 t; cvta.to.shared.u64 t, %1; cvt.u32.u64 %0, t; }" : "=r"(a) : "l"(p));
    return a;
}
__device__ __forceinline__ void cp_async16(uint32_t dst, const void* src) {
    asm volatile("cp.async.cg.shared.global [%0], [%1], 16;" :: "r"(dst), "l"(src));
}
#define CP_COMMIT()  asm volatile("cp.async.commit_group;" ::: "memory")
#define CP_WAIT2()   asm volatile("cp.async.wait_group 2;" ::: "memory")

__device__ __forceinline__ void ldsm4(uint32_t& r0, uint32_t& r1, uint32_t& r2, uint32_t& r3,
                                      uint32_t a) {
    asm volatile("ldmatrix.sync.aligned.m8n8.x4.shared.b16 {%0,%1,%2,%3}, [%4];"
                 : "=r"(r0), "=r"(r1), "=r"(r2), "=r"(r3) : "r"(a));
}

__device__ __forceinline__ void mma16816(float* c, const uint32_t* a, const uint32_t* b) {
    asm volatile(
        "mma.sync.aligned.m16n8k16.row.col.f32.f16.f16.f32 "
        "{%0,%1,%2,%3}, {%4,%5,%6,%7}, {%8,%9}, {%0,%1,%2,%3};"
        : "+f"(c[0]), "+f"(c[1]), "+f"(c[2]), "+f"(c[3])
        : "r"(a[0]), "r"(a[1]), "r"(a[2]), "r"(a[3]), "r"(b[0]), "r"(b[1]));
}

// ---------------------------------------------------------------------------
// Prep kernel (merged): Wout transpose + S computation
// ---------------------------------------------------------------------------
#define NB_TR ((Hh/32) * (KC/32))   // 4352

__global__ void __launch_bounds__(256) prep_kernel(
    const float* __restrict__ W,      // Wout [2176][2048]
    const float* __restrict__ Wk,     // [8][32][2048]
    const float* __restrict__ st)     // slot_tables [8][16][32]
{
    __shared__ float tile[32][33];
    __shared__ float s[PKk];
    int b = blockIdx.x;
    int tid = threadIdx.x;

    if (b < NB_TR) {
        int n0 = (b % (Hh/32)) * 32;
        int k0 = (b / (Hh/32)) * 32;
        int tx = tid & 31, ty = tid >> 5;
        #pragma unroll
        for (int i = 0; i < 32; i += 8)
            tile[ty + i][tx] = W[(size_t)(k0 + ty + i) * Hh + n0 + tx];
        __syncthreads();
        #pragma unroll
        for (int i = 0; i < 32; i += 8) {
            float v = tile[tx][ty + i];
            g_B2[(size_t)(n0 + ty + i) * KC + k0 + tx] = __float2half(v);
        }
    } else {
        int mn = b - NB_TR;                  // 0..127
        int m = mn >> 4;
        if (tid < PKk) {
            float v = st[mn*PKk + tid];
            float ss = v*v;
            #pragma unroll
            for (int o = 16; o > 0; o >>= 1) ss += __shfl_xor_sync(0xffffffffu, ss, o);
            float inv = 1.0f / fmaxf(sqrtf(ss), 1e-12f);
            s[tid] = v * inv;
        }
        __syncthreads();
        const float* wb = Wk + (size_t)m * PKk * Hh;
        for (int h = tid; h < Hh; h += 256) {
            float acc = 0.f;
            #pragma unroll
            for (int k = 0; k < PKk; k++) acc += wb[(size_t)k*Hh + h] * s[k];
            __half hi, lo; split2h(acc, hi, lo);
            g_Shi[(size_t)mn*Hh + h] = hi;
            g_Slo[(size_t)mn*Hh + h] = lo;
        }
    }
}

// ---------------------------------------------------------------------------
// RMSNorm -> hi/lo fp16 split into combined buffer cols [128, 2176)
// ---------------------------------------------------------------------------
__global__ void rmsnorm_kernel(const float* __restrict__ x, const float* __restrict__ w) {
    __shared__ float red[8];
    int t   = blockIdx.x;
    int tid = threadIdx.x;
    const float4* xr = (const float4*)(x + (size_t)t * Hh);
    float4 v0 = xr[tid];
    float4 v1 = xr[tid + 256];
    float ss = v0.x*v0.x + v0.y*v0.y + v0.z*v0.z + v0.w*v0.w
             + v1.x*v1.x + v1.y*v1.y + v1.z*v1.z + v1.w*v1.w;
    int lane = tid & 31, wp = tid >> 5;
    #pragma unroll
    for (int o = 16; o > 0; o >>= 1) ss += __shfl_xor_sync(0xffffffffu, ss, o);
    if (lane == 0) red[wp] = ss;
    __syncthreads();
    if (wp == 0) {
        float v = (lane < 8) ? red[lane] : 0.f;
        #pragma unroll
        for (int o = 4; o > 0; o >>= 1) v += __shfl_xor_sync(0xffffffffu, v, o);
        if (lane == 0) red[0] = v;
    }
    __syncthreads();
    float scale = rsqrtf(red[0] * (1.0f / Hh) + 1e-6f);

    const float4* wr = (const float4*)w;
    float4 w0 = wr[tid], w1 = wr[tid + 256];
    float o0[4] = { v0.x*scale*w0.x, v0.y*scale*w0.y, v0.z*scale*w0.z, v0.w*scale*w0.w };
    float o1[4] = { v1.x*scale*w1.x, v1.y*scale*w1.y, v1.z*scale*w1.z, v1.w*scale*w1.w };

    __half* dh = g_Ahi + (size_t)t * KC + 128;
    __half* dl = g_Alo + (size_t)t * KC + 128;
    #pragma unroll
    for (int j = 0; j < 4; j++) {
        __half hi, lo;
        split2h(o0[j], hi, lo); dh[tid*4 + j] = hi; dl[tid*4 + j] = lo;
        split2h(o1[j], hi, lo); dh[(tid+256)*4 + j] = hi; dl[(tid+256)*4 + j] = lo;
    }
}

// ---------------------------------------------------------------------------
// Shared GEMM tiling constants
// ---------------------------------------------------------------------------
#define BM 128
#define BN 128
#define BK 32
#define ROWB 80
#define TILEB (128*ROWB)

// ===========================================================================
// GEMM-S: sims = h @ S^T, 3-pass fp16 split, fused argmax + emb gather.
// Register-double-buffered fragments; 1 CTA/SM.
// ===========================================================================
#define S3_STAGES 4
#define S3_STAGEB (4*TILEB)
#define S3_SMEM (S3_STAGES*S3_STAGEB)
#define T3_AHI 0
#define T3_ALO TILEB
#define T3_BHI (2*TILEB)
#define T3_BLO (3*TILEB)

__device__ __forceinline__ void prefetch3(uint32_t sbase, int bm, int kb, int tid)
{
    const __half* Ah = g_Ahi + 128;
    const __half* Al = g_Alo + 128;
    #pragma unroll
    for (int q = 0; q < 2; q++) {
        int idx = tid + q*256;
        int row = idx >> 2, ch = idx & 3;
        uint32_t soff = (uint32_t)row*ROWB + ch*16;
        cp_async16(sbase + T3_AHI + soff, Ah + (size_t)(bm+row)*KC + kb + ch*8);
    }
    #pragma unroll
    for (int q = 0; q < 2; q++) {
        int idx = tid + q*256;
        int row = idx >> 2, ch = idx & 3;
        uint32_t soff = (uint32_t)row*ROWB + ch*16;
        cp_async16(sbase + T3_ALO + soff, Al + (size_t)(bm+row)*KC + kb + ch*8);
    }
    #pragma unroll
    for (int q = 0; q < 2; q++) {
        int idx = tid + q*256;
        int row = idx >> 2, ch = idx & 3;
        uint32_t soff = (uint32_t)row*ROWB + ch*16;
        cp_async16(sbase + T3_BHI + soff, g_Shi + (size_t)row*Hh + kb + ch*8);
    }
    #pragma unroll
    for (int q = 0; q < 2; q++) {
        int idx = tid + q*256;
        int row = idx >> 2, ch = idx & 3;
        uint32_t soff = (uint32_t)row*ROWB + ch*16;
        cp_async16(sbase + T3_BLO + soff, g_Slo + (size_t)row*Hh + kb + ch*8);
    }
}

__device__ __forceinline__ void ldfrag3(
    uint32_t sbase, uint32_t aoff, uint32_t boff, int k16,
    uint32_t ah[4][4], uint32_t al[4][4], uint32_t bh[4][2], uint32_t bl[4][2])
{
    uint32_t kbyte = k16*32;
    uint32_t stAhi = sbase + T3_AHI, stAlo = sbase + T3_ALO;
    uint32_t stBhi = sbase + T3_BHI, stBlo = sbase + T3_BLO;
    #pragma unroll
    for (int i = 0; i < 4; i++) {
        ldsm4(ah[i][0], ah[i][1], ah[i][2], ah[i][3], stAhi + aoff + i*16*ROWB + kbyte);
        ldsm4(al[i][0], al[i][1], al[i][2], al[i][3], stAlo + aoff + i*16*ROWB + kbyte);
    }
    ldsm4(bh[0][0], bh[0][1], bh[1][0], bh[1][1], stBhi + boff + kbyte);
    ldsm4(bh[2][0], bh[2][1], bh[3][0], bh[3][1], stBhi + boff + 16*ROWB + kbyte);
    ldsm4(bl[0][0], bl[0][1], bl[1][0], bl[1][1], stBlo + boff + kbyte);
    ldsm4(bl[2][0], bl[2][1], bl[3][0], bl[3][1], stBlo + boff + 16*ROWB + kbyte);
}

__global__ void __launch_bounds__(256) gemms_kernel(const float* __restrict__ emb) {
    extern __shared__ char smem[];
    __shared__ int idx_s[128][8];
    uint32_t sb = smem_u32(smem);
    int tid = threadIdx.x;
    int wid = tid >> 5, lane = tid & 31;
    int wm = wid >> 2, wn = wid & 3;
    int rq = lane >> 2, tq = lane & 3;
    int bm = blockIdx.x * BM;
    const int nK = Hh / BK;   // 64

    uint32_t aoff = (uint32_t)(wm*64 + (lane & 15))*ROWB + ((lane >> 4) & 1)*16;
    uint32_t boff = (uint32_t)(wn*32 + (lane & 7) + ((lane & 16) >> 1))*ROWB + ((lane & 8) << 1);

    float c[4][4][4] = {};
    uint32_t ah0[4][4], al0[4][4], bh0[4][2], bl0[4][2];
    uint32_t ah1[4][4], al1[4][4], bh1[4][2], bl1[4][2];

    prefetch3(sb + 0*S3_STAGEB, bm, 0,    tid); CP_COMMIT();
    prefetch3(sb + 1*S3_STAGEB, bm, BK,   tid); CP_COMMIT();
    prefetch3(sb + 2*S3_STAGEB, bm, 2*BK, tid); CP_COMMIT();
    CP_WAIT2();
    __syncthreads();
    ldfrag3(sb + 0*S3_STAGEB, aoff, boff, 0, ah0, al0, bh0, bl0);

    int stage = 0;
    for (int kt = 0; kt < nK; kt++) {
        ldfrag3(sb + stage*S3_STAGEB, aoff, boff, 1, ah1, al1, bh1, bl1);
        if (kt + 3 < nK) {
            int ps = stage + 3; if (ps >= S3_STAGES) ps -= S3_STAGES;
            prefetch3(sb + ps*S3_STAGEB, bm, (kt+3)*BK, tid);
        }
        CP_COMMIT();
        #pragma unroll
        for (int i = 0; i < 4; i++)
            #pragma unroll
            for (int j = 0; j < 4; j++) {
                mma16816(c[i][j], ah0[i], bh0[j]);
                mma16816(c[i][j], ah0[i], bl0[j]);
                mma16816(c[i][j], al0[i], bh0[j]);
            }
        if (kt + 1 < nK) {
            CP_WAIT2();
            __syncthreads();
            int ns = stage + 1; if (ns >= S3_STAGES) ns = 0;
            ldfrag3(sb + ns*S3_STAGEB, aoff, boff, 0, ah0, al0, bh0, bl0);
        }
        #pragma unroll
        for (int i = 0; i < 4; i++)
            #pragma unroll
            for (int j = 0; j < 4; j++) {
                mma16816(c[i][j], ah1[i], bh1[j]);
                mma16816(c[i][j], ah1[i], bl1[j]);
                mma16816(c[i][j], al1[i], bh1[j]);
            }
        stage++; if (stage >= S3_STAGES) stage = 0;
    }

    // Fused argmax epilogue: per row, per m-group (16 slots), first-max-wins.
    #pragma unroll
    for (int i = 0; i < 4; i++) {
        #pragma unroll
        for (int half = 0; half < 2; half++) {
            #pragma unroll
            for (int mg = 0; mg < 2; mg++) {
                float bv = c[i][mg*2][half*2+0]; int bs = tq*2;
                float v  = c[i][mg*2][half*2+1];
                if (v > bv) { bv = v; bs = tq*2+1; }
                v = c[i][mg*2+1][half*2+0];
                if (v > bv) { bv = v; bs = 8+tq*2; }
                v = c[i][mg*2+1][half*2+1];
                if (v > bv) { bv = v; bs = 8+tq*2+1; }
                #pragma unroll
                for (int o = 1; o <= 2; o <<= 1) {
                    float ov = __shfl_xor_sync(0xffffffffu, bv, o);
                    int   os = __shfl_xor_sync(0xffffffffu, bs, o);
                    if (ov > bv || (ov == bv && os < bs)) { bv = ov; bs = os; }
                }
                if (tq == 0)
                    idx_s[wm*64 + i*16 + half*8 + rq][2*wn + mg] = bs;
            }
        }
    }
    __syncthreads();

    // Gather + mean + fp16 split into combined cols [0,128)
    {
        int r  = tid >> 1;
        int c0 = (tid & 1) * 64;
        int ids[8];
        #pragma unroll
        for (int g = 0; g < 8; g++) ids[g] = idx_s[r][g];
        __half* dh = g_Ahi + (size_t)(bm + r) * KC + c0;
        __half* dl = g_Alo + (size_t)(bm + r) * KC + c0;
        for (int cc = 0; cc < 64; cc += 4) {
            float4 acc = {0.f, 0.f, 0.f, 0.f};
            #pragma unroll
            for (int g = 0; g < 8; g++) {
                float4 e = *(const float4*)(emb + ids[g]*Vv + c0 + cc);
                acc.x += e.x; acc.y += e.y; acc.z += e.z; acc.w += e.w;
            }
            __half hi, lo;
            split2h(acc.x * 0.125f, hi, lo); dh[cc+0] = hi; dl[cc+0] = lo;
            split2h(acc.y * 0.125f, hi, lo); dh[cc+1] = hi; dl[cc+1] = lo;
            split2h(acc.z * 0.125f, hi, lo); dh[cc+2] = hi; dl[cc+2] = lo;
            split2h(acc.w * 0.125f, hi, lo); dh[cc+3] = hi; dl[cc+3] = lo;
        }
    }
}

// ===========================================================================
// GEMM2: out = x + combined(fp16) @ Wout^T(fp16), single pass.
// Register-double-buffered fragments; 1 CTA/SM, regs free up to 255.
// ===========================================================================
#define S1_STAGES 4
#define S1_STAGEB (2*TILEB)
#define S1_SMEM (S1_STAGES*S1_STAGEB)
#define T1_A 0
#define T1_B TILEB

__device__ __forceinline__ void prefetch1(uint32_t sbase, int bm, int bn, int kb, int tid)
{
    #pragma unroll
    for (int q = 0; q < 2; q++) {
        int idx = tid + q*256;
        int row = idx >> 2, ch = idx & 3;
        uint32_t soff = (uint32_t)row*ROWB + ch*16;
        cp_async16(sbase + T1_A + soff, g_Ahi + (size_t)(bm+row)*KC + kb + ch*8);
    }
    #pragma unroll
    for (int q = 0; q < 2; q++) {
        int idx = tid + q*256;
        int row = idx >> 2, ch = idx & 3;
        uint32_t soff = (uint32_t)row*ROWB + ch*16;
        cp_async16(sbase + T1_B + soff, g_B2 + (size_t)(bn+row)*KC + kb + ch*8);
    }
}

__device__ __forceinline__ void ldfrag1(
    uint32_t sbase, uint32_t aoff, uint32_t boff, int k16,
    uint32_t a[4][4], uint32_t b[4][2])
{
    uint32_t kbyte = k16*32;
    uint32_t stA = sbase + T1_A, stB = sbase + T1_B;
    #pragma unroll
    for (int i = 0; i < 4; i++)
        ldsm4(a[i][0], a[i][1], a[i][2], a[i][3], stA + aoff + i*16*ROWB + kbyte);
    ldsm4(b[0][0], b[0][1], b[1][0], b[1][1], stB + boff + kbyte);
    ldsm4(b[2][0], b[2][1], b[3][0], b[3][1], stB + boff + 16*ROWB + kbyte);
}

__global__ void __launch_bounds__(256) gemm2_kernel(
    const float* __restrict__ resid, float* __restrict__ outp)
{
    extern __shared__ char smem[];
    uint32_t sb = smem_u32(smem);
    int tid = threadIdx.x;
    int wid = tid >> 5, lane = tid & 31;
    int wm = wid >> 2, wn = wid & 3;
    int rq = lane >> 2, tq = lane & 3;
    int bm = blockIdx.y * BM;
    int bn = blockIdx.x * BN;
    const int nK = KC / BK;  // 68

    uint32_t aoff = (uint32_t)(wm*64 + (lane & 15))*ROWB + ((lane >> 4) & 1)*16;
    uint32_t boff = (uint32_t)(wn*32 + (lane & 7) + ((lane & 16) >> 1))*ROWB + ((lane & 8) << 1);

    float c[4][4][4] = {};
    uint32_t a0[4][4], b0[4][2], a1[4][4], b1[4][2];

    prefetch1(sb + 0*S1_STAGEB, bm, bn, 0,    tid); CP_COMMIT();
    prefetch1(sb + 1*S1_STAGEB, bm, bn, BK,   tid); CP_COMMIT();
    prefetch1(sb + 2*S1_STAGEB, bm, bn, 2*BK, tid); CP_COMMIT();
    CP_WAIT2();
    __syncthreads();
    ldfrag1(sb + 0*S1_STAGEB, aoff, boff, 0, a0, b0);

    int stage = 0;
    for (int kt = 0; kt < nK; kt++) {
        ldfrag1(sb + stage*S1_STAGEB, aoff, boff, 1, a1, b1);
        if (kt + 3 < nK) {
            int ps = stage + 3; if (ps >= S1_STAGES) ps -= S1_STAGES;
            prefetch1(sb + ps*S1_STAGEB, bm, bn, (kt+3)*BK, tid);
        }
        CP_COMMIT();
        #pragma unroll
        for (int i = 0; i < 4; i++)
            #pragma unroll
            for (int j = 0; j < 4; j++)
                mma16816(c[i][j], a0[i], b0[j]);
        if (kt + 1 < nK) {
            CP_WAIT2();
            __syncthreads();
            int ns = stage + 1; if (ns >= S1_STAGES) ns = 0;
            ldfrag1(sb + ns*S1_STAGEB, aoff, boff, 0, a0, b0);
        }
        #pragma unroll
        for (int i = 0; i < 4; i++)
            #pragma unroll
            for (int j = 0; j < 4; j++)
                mma16816(c[i][j], a1[i], b1[j]);
        stage++; if (stage >= S1_STAGES) stage = 0;
    }

    // Epilogue: residual add
    #pragma unroll
    for (int i = 0; i < 4; i++) {
        int row0 = bm + wm*64 + i*16 + rq;
        #pragma unroll
        for (int j = 0; j < 4; j++) {
            int col = bn + wn*32 + j*8 + tq*2;
            size_t o0 = (size_t)row0 * Hh + col;
            size_t o1 = (size_t)(row0 + 8) * Hh + col;
            float2 r0 = *(const float2*)(resid + o0);
            float2 r1 = *(const float2*)(resid + o1);
            float2 v0 = { r0.x + c[i][j][0], r0.y + c[i][j][1] };
            float2 v1 = { r1.x + c[i][j][2], r1.y + c[i][j][3] };
            *(float2*)(outp + o0) = v0;
            *(float2*)(outp + o1) = v1;
        }
    }
}

// ---------------------------------------------------------------------------
// Host launcher
// ---------------------------------------------------------------------------
extern "C" void kernel_launch(void* const* d_in, const int* in_sizes, int n_in,
                              void* d_out, int out_size) {
    const float* x    = (const float*)d_in[0];
    const float* ln_w = (const float*)d_in[1];
    const float* Wk   = (const float*)d_in[2];
    const float* st   = (const float*)d_in[3];
    const float* emb  = (const float*)d_in[4];
    const float* Wout = (const float*)d_in[5];
    float* out = (float*)d_out;

    cudaFuncSetAttribute(gemms_kernel, cudaFuncAttributeMaxDynamicSharedMemorySize, S3_SMEM);
    cudaFuncSetAttribute(gemm2_kernel, cudaFuncAttributeMaxDynamicSharedMemorySize, S1_SMEM);

    // Launch order keeps gemm2 as the 4th launch (the one ncu samples).
    prep_kernel<<<NB_TR + 128, 256>>>(Wout, Wk, st);
    rmsnorm_kernel<<<Tt, 256>>>(x, ln_w);

    // GEMM-S: sims + argmax + gather -> writes mem into combined cols [0,128)
    gemms_kernel<<<Tt/BM, 256, S3_SMEM>>>(emb);

    // GEMM2: out = x + combined @ Wout^T
    gemm2_kernel<<<dim3(Hh/BN, Tt/BM), 256, S1_SMEM>>>(x, out);
}

// round 11
// speedup vs baseline: 1.1758x; 1.1758x over previous
#include <cuda_runtime.h>
#include <cuda_fp16.h>
#include <cstdint>

// Problem dims (fixed by the dataset)
#define Bb 4
#define Ss 4096
#define Tt (Bb*Ss)     // 16384 tokens
#define Hh 2048
#define Mm 8
#define PKk 32
#define NSn 16
#define Vv 128
#define KC (Vv+Hh)     // 2176

// ---------------------------------------------------------------------------
// Global scratch (static __device__ arrays; allocation-free)
// ---------------------------------------------------------------------------
__device__ __align__(16) __half g_Ahi[(size_t)Tt*KC];   // combined [mem|h] hi fp16
__device__ __align__(16) __half g_Alo[(size_t)Tt*KC];   // combined [mem|h] lo fp16
__device__ __align__(16) __half g_B2 [(size_t)Hh*KC];   // Wout^T fp16 [2048][2176]
__device__ __align__(16) __half g_Shi[(size_t)128*Hh];  // S = Wk^T @ sln, hi [128][2048]
__device__ __align__(16) __half g_Slo[(size_t)128*Hh];  // S lo

__device__ __forceinline__ void split2h(float v, __half& hi, __half& lo) {
    hi = __float2half(v);
    lo = __float2half(v - __half2float(hi));
}

__device__ __forceinline__ uint32_t smem_u32(const void* p) {
    uint32_t a;
    asm("{ .reg .u64 t; cvta.to.shared.u64 t, %1; cvt.u32.u64 %0, t; }" : "=r"(a) : "l"(p));
    return a;
}
__device__ __forceinline__ void cp_async16(uint32_t dst, const void* src) {
    asm volatile("cp.async.cg.shared.global [%0], [%1], 16;" :: "r"(dst), "l"(src));
}
#define CP_COMMIT()  asm volatile("cp.async.commit_group;" ::: "memory")
#define CP_WAIT1()   asm volatile("cp.async.wait_group 1;" ::: "memory")

__device__ __forceinline__ void ldsm4(uint32_t& r0, uint32_t& r1, uint32_t& r2, uint32_t& r3,
                                      uint32_t a) {
    asm volatile("ldmatrix.sync.aligned.m8n8.x4.shared.b16 {%0,%1,%2,%3}, [%4];"
                 : "=r"(r0), "=r"(r1), "=r"(r2), "=r"(r3) : "r"(a));
}

__device__ __forceinline__ void mma16816(float* c, const uint32_t* a, const uint32_t* b) {
    asm volatile(
        "mma.sync.aligned.m16n8k16.row.col.f32.f16.f16.f32 "
        "{%0,%1,%2,%3}, {%4,%5,%6,%7}, {%8,%9}, {%0,%1,%2,%3};"
        : "+f"(c[0]), "+f"(c[1]), "+f"(c[2]), "+f"(c[3])
        : "r"(a[0]), "r"(a[1]), "r"(a[2]), "r"(a[3]), "r"(b[0]), "r"(b[1]));
}

// ---------------------------------------------------------------------------
// Prep kernel (merged): Wout transpose + S computation
// ---------------------------------------------------------------------------
#define NB_TR ((Hh/32) * (KC/32))   // 4352

__global__ void __launch_bounds__(256) prep_kernel(
    const float* __restrict__ W,      // Wout [2176][2048]
    const float* __restrict__ Wk,     // [8][32][2048]
    const float* __restrict__ st)     // slot_tables [8][16][32]
{
    __shared__ float tile[32][33];
    __shared__ float s[PKk];
    int b = blockIdx.x;
    int tid = threadIdx.x;

    if (b < NB_TR) {
        int n0 = (b % (Hh/32)) * 32;
        int k0 = (b / (Hh/32)) * 32;
        int tx = tid & 31, ty = tid >> 5;
        #pragma unroll
        for (int i = 0; i < 32; i += 8)
            tile[ty + i][tx] = W[(size_t)(k0 + ty + i) * Hh + n0 + tx];
        __syncthreads();
        #pragma unroll
        for (int i = 0; i < 32; i += 8) {
            float v = tile[tx][ty + i];
            g_B2[(size_t)(n0 + ty + i) * KC + k0 + tx] = __float2half(v);
        }
    } else {
        int mn = b - NB_TR;                  // 0..127
        int m = mn >> 4;
        if (tid < PKk) {
            float v = st[mn*PKk + tid];
            float ss = v*v;
            #pragma unroll
            for (int o = 16; o > 0; o >>= 1) ss += __shfl_xor_sync(0xffffffffu, ss, o);
            float inv = 1.0f / fmaxf(sqrtf(ss), 1e-12f);
            s[tid] = v * inv;
        }
        __syncthreads();
        const float* wb = Wk + (size_t)m * PKk * Hh;
        for (int h = tid; h < Hh; h += 256) {
            float acc = 0.f;
            #pragma unroll
            for (int k = 0; k < PKk; k++) acc += wb[(size_t)k*Hh + h] * s[k];
            __half hi, lo; split2h(acc, hi, lo);
            g_Shi[(size_t)mn*Hh + h] = hi;
            g_Slo[(size_t)mn*Hh + h] = lo;
        }
    }
}

// ---------------------------------------------------------------------------
// RMSNorm -> hi/lo fp16 split into combined buffer cols [128, 2176)
// ---------------------------------------------------------------------------
__global__ void rmsnorm_kernel(const float* __restrict__ x, const float* __restrict__ w) {
    __shared__ float red[8];
    int t   = blockIdx.x;
    int tid = threadIdx.x;
    const float4* xr = (const float4*)(x + (size_t)t * Hh);
    float4 v0 = xr[tid];
    float4 v1 = xr[tid + 256];
    float ss = v0.x*v0.x + v0.y*v0.y + v0.z*v0.z + v0.w*v0.w
             + v1.x*v1.x + v1.y*v1.y + v1.z*v1.z + v1.w*v1.w;
    int lane = tid & 31, wp = tid >> 5;
    #pragma unroll
    for (int o = 16; o > 0; o >>= 1) ss += __shfl_xor_sync(0xffffffffu, ss, o);
    if (lane == 0) red[wp] = ss;
    __syncthreads();
    if (wp == 0) {
        float v = (lane < 8) ? red[lane] : 0.f;
        #pragma unroll
        for (int o = 4; o > 0; o >>= 1) v += __shfl_xor_sync(0xffffffffu, v, o);
        if (lane == 0) red[0] = v;
    }
    __syncthreads();
    float scale = rsqrtf(red[0] * (1.0f / Hh) + 1e-6f);

    const float4* wr = (const float4*)w;
    float4 w0 = wr[tid], w1 = wr[tid + 256];
    float o0[4] = { v0.x*scale*w0.x, v0.y*scale*w0.y, v0.z*scale*w0.z, v0.w*scale*w0.w };
    float o1[4] = { v1.x*scale*w1.x, v1.y*scale*w1.y, v1.z*scale*w1.z, v1.w*scale*w1.w };

    __half* dh = g_Ahi + (size_t)t * KC + 128;
    __half* dl = g_Alo + (size_t)t * KC + 128;
    #pragma unroll
    for (int j = 0; j < 4; j++) {
        __half hi, lo;
        split2h(o0[j], hi, lo); dh[tid*4 + j] = hi; dl[tid*4 + j] = lo;
        split2h(o1[j], hi, lo); dh[(tid+256)*4 + j] = hi; dl[(tid+256)*4 + j] = lo;
    }
}

// ---------------------------------------------------------------------------
// Shared GEMM tiling constants: BK=64, 3-stage ring
// ---------------------------------------------------------------------------
#define BM 128
#define BN 128
#define BK 64
#define ROWB 144                // 128B data + 16B pad; 8-row ldmatrix hits all 32 banks
#define TILEB (128*ROWB)        // 18432 B per tile

// ===========================================================================
// GEMM-S: sims = h @ S^T, 3-pass fp16 split, fused argmax + emb gather.
// ===========================================================================
#define S3_STAGES 3
#define S3_STAGEB (4*TILEB)
#define S3_SMEM (S3_STAGES*S3_STAGEB)   // 221184 B
#define T3_AHI 0
#define T3_ALO TILEB
#define T3_BHI (2*TILEB)
#define T3_BLO (3*TILEB)

__device__ __forceinline__ void prefetch3(uint32_t sbase, int bm, int kb, int tid)
{
    const __half* Ah = g_Ahi + 128;
    const __half* Al = g_Alo + 128;
    #pragma unroll
    for (int q = 0; q < 4; q++) {
        int idx = tid + q*256;               // 0..1023
        int row = idx >> 3, ch = idx & 7;
        uint32_t soff = (uint32_t)row*ROWB + ch*16;
        cp_async16(sbase + T3_AHI + soff, Ah + (size_t)(bm+row)*KC + kb + ch*8);
    }
    #pragma unroll
    for (int q = 0; q < 4; q++) {
        int idx = tid + q*256;
        int row = idx >> 3, ch = idx & 7;
        uint32_t soff = (uint32_t)row*ROWB + ch*16;
        cp_async16(sbase + T3_ALO + soff, Al + (size_t)(bm+row)*KC + kb + ch*8);
    }
    #pragma unroll
    for (int q = 0; q < 4; q++) {
        int idx = tid + q*256;
        int row = idx >> 3, ch = idx & 7;
        uint32_t soff = (uint32_t)row*ROWB + ch*16;
        cp_async16(sbase + T3_BHI + soff, g_Shi + (size_t)row*Hh + kb + ch*8);
    }
    #pragma unroll
    for (int q = 0; q < 4; q++) {
        int idx = tid + q*256;
        int row = idx >> 3, ch = idx & 7;
        uint32_t soff = (uint32_t)row*ROWB + ch*16;
        cp_async16(sbase + T3_BLO + soff, g_Slo + (size_t)row*Hh + kb + ch*8);
    }
}

__global__ void __launch_bounds__(256) gemms_kernel(const float* __restrict__ emb) {
    extern __shared__ char smem[];
    __shared__ int idx_s[128][8];
    uint32_t sb = smem_u32(smem);
    int tid = threadIdx.x;
    int wid = tid >> 5, lane = tid & 31;
    int wm = wid >> 2, wn = wid & 3;
    int rq = lane >> 2, tq = lane & 3;
    int bm = blockIdx.x * BM;
    const int nK = Hh / BK;   // 32

    uint32_t aoff = (uint32_t)(wm*64 + (lane & 15))*ROWB + ((lane >> 4) & 1)*16;
    uint32_t boff = (uint32_t)(wn*32 + (lane & 7) + ((lane & 16) >> 1))*ROWB + ((lane & 8) << 1);

    float c[4][4][4] = {};

    prefetch3(sb + 0*S3_STAGEB, bm, 0,  tid); CP_COMMIT();
    prefetch3(sb + 1*S3_STAGEB, bm, BK, tid); CP_COMMIT();

    int stage = 0;
    for (int kt = 0; kt < nK; kt++) {
        CP_WAIT1();
        __syncthreads();
        if (kt + 2 < nK) {
            int ps = stage + 2; if (ps >= S3_STAGES) ps -= S3_STAGES;
            prefetch3(sb + ps*S3_STAGEB, bm, (kt+2)*BK, tid);
        }
        CP_COMMIT();

        uint32_t stAhi = sb + stage*S3_STAGEB + T3_AHI;
        uint32_t stAlo = sb + stage*S3_STAGEB + T3_ALO;
        uint32_t stBhi = sb + stage*S3_STAGEB + T3_BHI;
        uint32_t stBlo = sb + stage*S3_STAGEB + T3_BLO;

        #pragma unroll
        for (int k16 = 0; k16 < 4; k16++) {
            uint32_t kbyte = k16*32;
            uint32_t ah[4][4], al[4][4];
            #pragma unroll
            for (int i = 0; i < 4; i++) {
                ldsm4(ah[i][0], ah[i][1], ah[i][2], ah[i][3], stAhi + aoff + i*16*ROWB + kbyte);
                ldsm4(al[i][0], al[i][1], al[i][2], al[i][3], stAlo + aoff + i*16*ROWB + kbyte);
            }
            uint32_t bh[4][2], bl[4][2];
            ldsm4(bh[0][0], bh[0][1], bh[1][0], bh[1][1], stBhi + boff + kbyte);
            ldsm4(bh[2][0], bh[2][1], bh[3][0], bh[3][1], stBhi + boff + 16*ROWB + kbyte);
            ldsm4(bl[0][0], bl[0][1], bl[1][0], bl[1][1], stBlo + boff + kbyte);
            ldsm4(bl[2][0], bl[2][1], bl[3][0], bl[3][1], stBlo + boff + 16*ROWB + kbyte);
            #pragma unroll
            for (int i = 0; i < 4; i++)
                #pragma unroll
                for (int j = 0; j < 4; j++) {
                    mma16816(c[i][j], ah[i], bh[j]);
                    mma16816(c[i][j], ah[i], bl[j]);
                    mma16816(c[i][j], al[i], bh[j]);
                }
        }
        __syncthreads();
        stage++; if (stage >= S3_STAGES) stage = 0;
    }

    // Fused argmax epilogue: per row, per m-group (16 slots), first-max-wins.
    #pragma unroll
    for (int i = 0; i < 4; i++) {
        #pragma unroll
        for (int half = 0; half < 2; half++) {
            #pragma unroll
            for (int mg = 0; mg < 2; mg++) {
                float bv = c[i][mg*2][half*2+0]; int bs = tq*2;
                float v  = c[i][mg*2][half*2+1];
                if (v > bv) { bv = v; bs = tq*2+1; }
                v = c[i][mg*2+1][half*2+0];
                if (v > bv) { bv = v; bs = 8+tq*2; }
                v = c[i][mg*2+1][half*2+1];
                if (v > bv) { bv = v; bs = 8+tq*2+1; }
                #pragma unroll
                for (int o = 1; o <= 2; o <<= 1) {
                    float ov = __shfl_xor_sync(0xffffffffu, bv, o);
                    int   os = __shfl_xor_sync(0xffffffffu, bs, o);
                    if (ov > bv || (ov == bv && os < bs)) { bv = ov; bs = os; }
                }
                if (tq == 0)
                    idx_s[wm*64 + i*16 + half*8 + rq][2*wn + mg] = bs;
            }
        }
    }
    __syncthreads();

    // Gather + mean + fp16 split into combined cols [0,128)
    {
        int r  = tid >> 1;
        int c0 = (tid & 1) * 64;
        int ids[8];
        #pragma unroll
        for (int g = 0; g < 8; g++) ids[g] = idx_s[r][g];
        __half* dh = g_Ahi + (size_t)(bm + r) * KC + c0;
        __half* dl = g_Alo + (size_t)(bm + r) * KC + c0;
        for (int cc = 0; cc < 64; cc += 4) {
            float4 acc = {0.f, 0.f, 0.f, 0.f};
            #pragma unroll
            for (int g = 0; g < 8; g++) {
                float4 e = *(const float4*)(emb + ids[g]*Vv + c0 + cc);
                acc.x += e.x; acc.y += e.y; acc.z += e.z; acc.w += e.w;
            }
            __half hi, lo;
            split2h(acc.x * 0.125f, hi, lo); dh[cc+0] = hi; dl[cc+0] = lo;
            split2h(acc.y * 0.125f, hi, lo); dh[cc+1] = hi; dl[cc+1] = lo;
            split2h(acc.z * 0.125f, hi, lo); dh[cc+2] = hi; dl[cc+2] = lo;
            split2h(acc.w * 0.125f, hi, lo); dh[cc+3] = hi; dl[cc+3] = lo;
        }
    }
}

// ===========================================================================
// GEMM2: out = x + combined(fp16) @ Wout^T(fp16), single pass.
// BK=64, 3-stage ring, 2 CTAs/SM (regs capped at 128).
// ===========================================================================
#define S1_STAGES 3
#define S1_STAGEB (2*TILEB)
#define S1_SMEM (S1_STAGES*S1_STAGEB)   // 110592 B
#define T1_A 0
#define T1_B TILEB

__device__ __forceinline__ void prefetch1(uint32_t sbase, int bm, int bn, int kb, int tid)
{
    #pragma unroll
    for (int q = 0; q < 4; q++) {
        int idx = tid + q*256;
        int row = idx >> 3, ch = idx & 7;
        uint32_t soff = (uint32_t)row*ROWB + ch*16;
        cp_async16(sbase + T1_A + soff, g_Ahi + (size_t)(bm+row)*KC + kb + ch*8);
    }
    #pragma unroll
    for (int q = 0; q < 4; q++) {
        int idx = tid + q*256;
        int row = idx >> 3, ch = idx & 7;
        uint32_t soff = (uint32_t)row*ROWB + ch*16;
        cp_async16(sbase + T1_B + soff, g_B2 + (size_t)(bn+row)*KC + kb + ch*8);
    }
}

__global__ void __launch_bounds__(256, 2) gemm2_kernel(
    const float* __restrict__ resid, float* __restrict__ outp)
{
    extern __shared__ char smem[];
    uint32_t sb = smem_u32(smem);
    int tid = threadIdx.x;
    int wid = tid >> 5, lane = tid & 31;
    int wm = wid >> 2, wn = wid & 3;
    int rq = lane >> 2, tq = lane & 3;
    int bm = blockIdx.y * BM;
    int bn = blockIdx.x * BN;
    const int nK = KC / BK;  // 34

    uint32_t aoff = (uint32_t)(wm*64 + (lane & 15))*ROWB + ((lane >> 4) & 1)*16;
    uint32_t boff = (uint32_t)(wn*32 + (lane & 7) + ((lane & 16) >> 1))*ROWB + ((lane & 8) << 1);

    float c[4][4][4] = {};

    prefetch1(sb + 0*S1_STAGEB, bm, bn, 0,  tid); CP_COMMIT();
    prefetch1(sb + 1*S1_STAGEB, bm, bn, BK, tid); CP_COMMIT();

    int stage = 0;
    for (int kt = 0; kt < nK; kt++) {
        CP_WAIT1();
        __syncthreads();
        if (kt + 2 < nK) {
            int ps = stage + 2; if (ps >= S1_STAGES) ps -= S1_STAGES;
            prefetch1(sb + ps*S1_STAGEB, bm, bn, (kt+2)*BK, tid);
        }
        CP_COMMIT();

        uint32_t stA = sb + stage*S1_STAGEB + T1_A;
        uint32_t stB = sb + stage*S1_STAGEB + T1_B;

        #pragma unroll
        for (int k16 = 0; k16 < 4; k16++) {
            uint32_t kbyte = k16*32;
            uint32_t a[4][4];
            #pragma unroll
            for (int i = 0; i < 4; i++)
                ldsm4(a[i][0], a[i][1], a[i][2], a[i][3], stA + aoff + i*16*ROWB + kbyte);
            uint32_t b[4][2];
            ldsm4(b[0][0], b[0][1], b[1][0], b[1][1], stB + boff + kbyte);
            ldsm4(b[2][0], b[2][1], b[3][0], b[3][1], stB + boff + 16*ROWB + kbyte);
            #pragma unroll
            for (int i = 0; i < 4; i++)
                #pragma unroll
                for (int j = 0; j < 4; j++)
                    mma16816(c[i][j], a[i], b[j]);
        }
        __syncthreads();
        stage++; if (stage >= S1_STAGES) stage = 0;
    }

    // Epilogue: residual add
    #pragma unroll
    for (int i = 0; i < 4; i++) {
        int row0 = bm + wm*64 + i*16 + rq;
        #pragma unroll
        for (int j = 0; j < 4; j++) {
            int col = bn + wn*32 + j*8 + tq*2;
            size_t o0 = (size_t)row0 * Hh + col;
            size_t o1 = (size_t)(row0 + 8) * Hh + col;
            float2 r0 = *(const float2*)(resid + o0);
            float2 r1 = *(const float2*)(resid + o1);
            float2 v0 = { r0.x + c[i][j][0], r0.y + c[i][j][1] };
            float2 v1 = { r1.x + c[i][j][2], r1.y + c[i][j][3] };
            *(float2*)(outp + o0) = v0;
            *(float2*)(outp + o1) = v1;
        }
    }
}

// ---------------------------------------------------------------------------
// Host launcher
// ---------------------------------------------------------------------------
extern "C" void kernel_launch(void* const* d_in, const int* in_sizes, int n_in,
                              void* d_out, int out_size) {
    const float* x    = (const float*)d_in[0];
    const float* ln_w = (const float*)d_in[1];
    const float* Wk   = (const float*)d_in[2];
    const float* st   = (const float*)d_in[3];
    const float* emb  = (const float*)d_in[4];
    const float* Wout = (const float*)d_in[5];
    float* out = (float*)d_out;

    cudaFuncSetAttribute(gemms_kernel, cudaFuncAttributeMaxDynamicSharedMemorySize, S3_SMEM);
    cudaFuncSetAttribute(gemm2_kernel, cudaFuncAttributeMaxDynamicSharedMemorySize, S1_SMEM);

    // Launch order keeps gemm2 as the 4th launch (the one ncu samples).
    prep_kernel<<<NB_TR + 128, 256>>>(Wout, Wk, st);
    rmsnorm_kernel<<<Tt, 256>>>(x, ln_w);

    // GEMM-S: sims + argmax + gather -> writes mem into combined cols [0,128)
    gemms_kernel<<<Tt/BM, 256, S3_SMEM>>>(emb);

    // GEMM2: out = x + combined @ Wout^T
    gemm2_kernel<<<dim3(Hh/BN, Tt/BM), 256, S1_SMEM>>>(x, out);
}

// round 13
// speedup vs baseline: 1.2256x; 1.0423x over previous
#include <cuda_runtime.h>
#include <cuda_fp16.h>
#include <cstdint>

// Problem dims (fixed by the dataset)
#define Bb 4
#define Ss 4096
#define Tt (Bb*Ss)     // 16384 tokens
#define Hh 2048
#define Mm 8
#define PKk 32
#define NSn 16
#define Vv 128
#define KC (Vv+Hh)     // 2176

// ---------------------------------------------------------------------------
// Global scratch (static __device__ arrays; allocation-free)
// ---------------------------------------------------------------------------
__device__ __align__(16) __half g_Ahi[(size_t)Tt*KC];   // combined [mem|h] hi fp16
__device__ __align__(16) __half g_Alo[(size_t)Tt*KC];   // combined [mem|h] lo fp16
__device__ __align__(16) __half g_B2 [(size_t)Hh*KC];   // Wout^T fp16 [2048][2176]
__device__ __align__(16) __half g_Shi[(size_t)128*Hh];  // S = Wk^T @ sln, hi [128][2048]
__device__ __align__(16) __half g_Slo[(size_t)128*Hh];  // S lo

__device__ __forceinline__ void split2h(float v, __half& hi, __half& lo) {
    hi = __float2half(v);
    lo = __float2half(v - __half2float(hi));
}

__device__ __forceinline__ uint32_t smem_u32(const void* p) {
    uint32_t a;
    asm("{ .reg .u64 t; cvta.to.shared.u64 t, %1; cvt.u32.u64 %0, t; }" : "=r"(a) : "l"(p));
    return a;
}
__device__ __forceinline__ void cp_async16(uint32_t dst, const void* src) {
    asm volatile("cp.async.cg.shared.global [%0], [%1], 16;" :: "r"(dst), "l"(src));
}
#define CP_COMMIT()  asm volatile("cp.async.commit_group;" ::: "memory")
#define CP_WAIT1()   asm volatile("cp.async.wait_group 1;" ::: "memory")

__device__ __forceinline__ void ldsm4(uint32_t& r0, uint32_t& r1, uint32_t& r2, uint32_t& r3,
                                      uint32_t a) {
    asm volatile("ldmatrix.sync.aligned.m8n8.x4.shared.b16 {%0,%1,%2,%3}, [%4];"
                 : "=r"(r0), "=r"(r1), "=r"(r2), "=r"(r3) : "r"(a));
}

__device__ __forceinline__ void mma16816(float* c, const uint32_t* a, const uint32_t* b) {
    asm volatile(
        "mma.sync.aligned.m16n8k16.row.col.f32.f16.f16.f32 "
        "{%0,%1,%2,%3}, {%4,%5,%6,%7}, {%8,%9}, {%0,%1,%2,%3};"
        : "+f"(c[0]), "+f"(c[1]), "+f"(c[2]), "+f"(c[3])
        : "r"(a[0]), "r"(a[1]), "r"(a[2]), "r"(a[3]), "r"(b[0]), "r"(b[1]));
}

// ---------------------------------------------------------------------------
// Prep kernel (merged): Wout transpose + S computation
// ---------------------------------------------------------------------------
#define NB_TR ((Hh/32) * (KC/32))   // 4352

__global__ void __launch_bounds__(256) prep_kernel(
    const float* __restrict__ W,      // Wout [2176][2048]
    const float* __restrict__ Wk,     // [8][32][2048]
    const float* __restrict__ st)     // slot_tables [8][16][32]
{
    __shared__ float tile[32][33];
    __shared__ float s[PKk];
    int b = blockIdx.x;
    int tid = threadIdx.x;

    if (b < NB_TR) {
        int n0 = (b % (Hh/32)) * 32;
        int k0 = (b / (Hh/32)) * 32;
        int tx = tid & 31, ty = tid >> 5;
        #pragma unroll
        for (int i = 0; i < 32; i += 8)
            tile[ty + i][tx] = W[(size_t)(k0 + ty + i) * Hh + n0 + tx];
        __syncthreads();
        #pragma unroll
        for (int i = 0; i < 32; i += 8) {
            float v = tile[tx][ty + i];
            g_B2[(size_t)(n0 + ty + i) * KC + k0 + tx] = __float2half(v);
        }
    } else {
        int mn = b - NB_TR;                  // 0..127
        int m = mn >> 4;
        if (tid < PKk) {
            float v = st[mn*PKk + tid];
            float ss = v*v;
            #pragma unroll
            for (int o = 16; o > 0; o >>= 1) ss += __shfl_xor_sync(0xffffffffu, ss, o);
            float inv = 1.0f / fmaxf(sqrtf(ss), 1e-12f);
            s[tid] = v * inv;
        }
        __syncthreads();
        const float* wb = Wk + (size_t)m * PKk * Hh;
        for (int h = tid; h < Hh; h += 256) {
            float acc = 0.f;
            #pragma unroll
            for (int k = 0; k < PKk; k++) acc += wb[(size_t)k*Hh + h] * s[k];
            __half hi, lo; split2h(acc, hi, lo);
            g_Shi[(size_t)mn*Hh + h] = hi;
            g_Slo[(size_t)mn*Hh + h] = lo;
        }
    }
}

// ---------------------------------------------------------------------------
// RMSNorm -> hi/lo fp16 split into combined buffer cols [128, 2176)
// ---------------------------------------------------------------------------
__global__ void rmsnorm_kernel(const float* __restrict__ x, const float* __restrict__ w) {
    __shared__ float red[8];
    int t   = blockIdx.x;
    int tid = threadIdx.x;
    const float4* xr = (const float4*)(x + (size_t)t * Hh);
    float4 v0 = xr[tid];
    float4 v1 = xr[tid + 256];
    float ss = v0.x*v0.x + v0.y*v0.y + v0.z*v0.z + v0.w*v0.w
             + v1.x*v1.x + v1.y*v1.y + v1.z*v1.z + v1.w*v1.w;
    int lane = tid & 31, wp = tid >> 5;
    #pragma unroll
    for (int o = 16; o > 0; o >>= 1) ss += __shfl_xor_sync(0xffffffffu, ss, o);
    if (lane == 0) red[wp] = ss;
    __syncthreads();
    if (wp == 0) {
        float v = (lane < 8) ? red[lane] : 0.f;
        #pragma unroll
        for (int o = 4; o > 0; o >>= 1) v += __shfl_xor_sync(0xffffffffu, v, o);
        if (lane == 0) red[0] = v;
    }
    __syncthreads();
    float scale = rsqrtf(red[0] * (1.0f / Hh) + 1e-6f);

    const float4* wr = (const float4*)w;
    float4 w0 = wr[tid], w1 = wr[tid + 256];
    float o0[4] = { v0.x*scale*w0.x, v0.y*scale*w0.y, v0.z*scale*w0.z, v0.w*scale*w0.w };
    float o1[4] = { v1.x*scale*w1.x, v1.y*scale*w1.y, v1.z*scale*w1.z, v1.w*scale*w1.w };

    __half* dh = g_Ahi + (size_t)t * KC + 128;
    __half* dl = g_Alo + (size_t)t * KC + 128;
    #pragma unroll
    for (int j = 0; j < 4; j++) {
        __half hi, lo;
        split2h(o0[j], hi, lo); dh[tid*4 + j] = hi; dl[tid*4 + j] = lo;
        split2h(o1[j], hi, lo); dh[(tid+256)*4 + j] = hi; dl[(tid+256)*4 + j] = lo;
    }
}

// ---------------------------------------------------------------------------
// Shared GEMM tiling constants: BK=64, 3-stage ring
// ---------------------------------------------------------------------------
#define BM 128
#define BN 128
#define BK 64
#define ROWB 144                // 128B data + 16B pad; 8-row ldmatrix hits all 32 banks
#define TILEB (128*ROWB)        // 18432 B per tile

// ===========================================================================
// GEMM-S: sims = h @ S^T, 3-pass fp16 split, fused argmax + emb gather.
// (unchanged from best-known config)
// ===========================================================================
#define S3_STAGES 3
#define S3_STAGEB (4*TILEB)
#define S3_SMEM (S3_STAGES*S3_STAGEB)   // 221184 B
#define T3_AHI 0
#define T3_ALO TILEB
#define T3_BHI (2*TILEB)
#define T3_BLO (3*TILEB)

__device__ __forceinline__ void prefetch3(uint32_t sbase, int bm, int kb, int tid)
{
    const __half* Ah = g_Ahi + 128;
    const __half* Al = g_Alo + 128;
    #pragma unroll
    for (int q = 0; q < 4; q++) {
        int idx = tid + q*256;               // 0..1023
        int row = idx >> 3, ch = idx & 7;
        uint32_t soff = (uint32_t)row*ROWB + ch*16;
        cp_async16(sbase + T3_AHI + soff, Ah + (size_t)(bm+row)*KC + kb + ch*8);
    }
    #pragma unroll
    for (int q = 0; q < 4; q++) {
        int idx = tid + q*256;
        int row = idx >> 3, ch = idx & 7;
        uint32_t soff = (uint32_t)row*ROWB + ch*16;
        cp_async16(sbase + T3_ALO + soff, Al + (size_t)(bm+row)*KC + kb + ch*8);
    }
    #pragma unroll
    for (int q = 0; q < 4; q++) {
        int idx = tid + q*256;
        int row = idx >> 3, ch = idx & 7;
        uint32_t soff = (uint32_t)row*ROWB + ch*16;
        cp_async16(sbase + T3_BHI + soff, g_Shi + (size_t)row*Hh + kb + ch*8);
    }
    #pragma unroll
    for (int q = 0; q < 4; q++) {
        int idx = tid + q*256;
        int row = idx >> 3, ch = idx & 7;
        uint32_t soff = (uint32_t)row*ROWB + ch*16;
        cp_async16(sbase + T3_BLO + soff, g_Slo + (size_t)row*Hh + kb + ch*8);
    }
}

__global__ void __launch_bounds__(256) gemms_kernel(const float* __restrict__ emb) {
    extern __shared__ char smem[];
    __shared__ int idx_s[128][8];
    uint32_t sb = smem_u32(smem);
    int tid = threadIdx.x;
    int wid = tid >> 5, lane = tid & 31;
    int wm = wid >> 2, wn = wid & 3;
    int rq = lane >> 2, tq = lane & 3;
    int bm = blockIdx.x * BM;
    const int nK = Hh / BK;   // 32

    uint32_t aoff = (uint32_t)(wm*64 + (lane & 15))*ROWB + ((lane >> 4) & 1)*16;
    uint32_t boff = (uint32_t)(wn*32 + (lane & 7) + ((lane & 16) >> 1))*ROWB + ((lane & 8) << 1);

    float c[4][4][4] = {};

    prefetch3(sb + 0*S3_STAGEB, bm, 0,  tid); CP_COMMIT();
    prefetch3(sb + 1*S3_STAGEB, bm, BK, tid); CP_COMMIT();

    int stage = 0;
    for (int kt = 0; kt < nK; kt++) {
        CP_WAIT1();
        __syncthreads();
        if (kt + 2 < nK) {
            int ps = stage + 2; if (ps >= S3_STAGES) ps -= S3_STAGES;
            prefetch3(sb + ps*S3_STAGEB, bm, (kt+2)*BK, tid);
        }
        CP_COMMIT();

        uint32_t stAhi = sb + stage*S3_STAGEB + T3_AHI;
        uint32_t stAlo = sb + stage*S3_STAGEB + T3_ALO;
        uint32_t stBhi = sb + stage*S3_STAGEB + T3_BHI;
        uint32_t stBlo = sb + stage*S3_STAGEB + T3_BLO;

        #pragma unroll
        for (int k16 = 0; k16 < 4; k16++) {
            uint32_t kbyte = k16*32;
            uint32_t ah[4][4], al[4][4];
            #pragma unroll
            for (int i = 0; i < 4; i++) {
                ldsm4(ah[i][0], ah[i][1], ah[i][2], ah[i][3], stAhi + aoff + i*16*ROWB + kbyte);
                ldsm4(al[i][0], al[i][1], al[i][2], al[i][3], stAlo + aoff + i*16*ROWB + kbyte);
            }
            uint32_t bh[4][2], bl[4][2];
            ldsm4(bh[0][0], bh[0][1], bh[1][0], bh[1][1], stBhi + boff + kbyte);
            ldsm4(bh[2][0], bh[2][1], bh[3][0], bh[3][1], stBhi + boff + 16*ROWB + kbyte);
            ldsm4(bl[0][0], bl[0][1], bl[1][0], bl[1][1], stBlo + boff + kbyte);
            ldsm4(bl[2][0], bl[2][1], bl[3][0], bl[3][1], stBlo + boff + 16*ROWB + kbyte);
            #pragma unroll
            for (int i = 0; i < 4; i++)
                #pragma unroll
                for (int j = 0; j < 4; j++) {
                    mma16816(c[i][j], ah[i], bh[j]);
                    mma16816(c[i][j], ah[i], bl[j]);
                    mma16816(c[i][j], al[i], bh[j]);
                }
        }
        __syncthreads();
        stage++; if (stage >= S3_STAGES) stage = 0;
    }

    // Fused argmax epilogue: per row, per m-group (16 slots), first-max-wins.
    #pragma unroll
    for (int i = 0; i < 4; i++) {
        #pragma unroll
        for (int half = 0; half < 2; half++) {
            #pragma unroll
            for (int mg = 0; mg < 2; mg++) {
                float bv = c[i][mg*2][half*2+0]; int bs = tq*2;
                float v  = c[i][mg*2][half*2+1];
                if (v > bv) { bv = v; bs = tq*2+1; }
                v = c[i][mg*2+1][half*2+0];
                if (v > bv) { bv = v; bs = 8+tq*2; }
                v = c[i][mg*2+1][half*2+1];
                if (v > bv) { bv = v; bs = 8+tq*2+1; }
                #pragma unroll
                for (int o = 1; o <= 2; o <<= 1) {
                    float ov = __shfl_xor_sync(0xffffffffu, bv, o);
                    int   os = __shfl_xor_sync(0xffffffffu, bs, o);
                    if (ov > bv || (ov == bv && os < bs)) { bv = ov; bs = os; }
                }
                if (tq == 0)
                    idx_s[wm*64 + i*16 + half*8 + rq][2*wn + mg] = bs;
            }
        }
    }
    __syncthreads();

    // Gather + mean + fp16 split into combined cols [0,128)
    {
        int r  = tid >> 1;
        int c0 = (tid & 1) * 64;
        int ids[8];
        #pragma unroll
        for (int g = 0; g < 8; g++) ids[g] = idx_s[r][g];
        __half* dh = g_Ahi + (size_t)(bm + r) * KC + c0;
        __half* dl = g_Alo + (size_t)(bm + r) * KC + c0;
        for (int cc = 0; cc < 64; cc += 4) {
            float4 acc = {0.f, 0.f, 0.f, 0.f};
            #pragma unroll
            for (int g = 0; g < 8; g++) {
                float4 e = *(const float4*)(emb + ids[g]*Vv + c0 + cc);
                acc.x += e.x; acc.y += e.y; acc.z += e.z; acc.w += e.w;
            }
            __half hi, lo;
            split2h(acc.x * 0.125f, hi, lo); dh[cc+0] = hi; dl[cc+0] = lo;
            split2h(acc.y * 0.125f, hi, lo); dh[cc+1] = hi; dl[cc+1] = lo;
            split2h(acc.z * 0.125f, hi, lo); dh[cc+2] = hi; dl[cc+2] = lo;
            split2h(acc.w * 0.125f, hi, lo); dh[cc+3] = hi; dl[cc+3] = lo;
        }
    }
}

// ===========================================================================
// GEMM2: out = x + combined(fp16) @ Wout^T(fp16), single pass.
// 512 threads, 4x4 warps with 32x32 warp tiles, BK=64, 3-stage ring,
// cross-barrier fragment double-buffering (one __syncthreads per iter).
// ===========================================================================
#define S1_STAGES 3
#define S1_STAGEB (2*TILEB)
#define S1_SMEM (S1_STAGES*S1_STAGEB)   // 110592 B
#define T1_A 0
#define T1_B TILEB

__device__ __forceinline__ void prefetch1(uint32_t sbase, int bm, int bn, int kb, int tid)
{
    #pragma unroll
    for (int q = 0; q < 2; q++) {
        int idx = tid + q*512;               // 0..1023
        int row = idx >> 3, ch = idx & 7;
        uint32_t soff = (uint32_t)row*ROWB + ch*16;
        cp_async16(sbase + T1_A + soff, g_Ahi + (size_t)(bm+row)*KC + kb + ch*8);
    }
    #pragma unroll
    for (int q = 0; q < 2; q++) {
        int idx = tid + q*512;
        int row = idx >> 3, ch = idx & 7;
        uint32_t soff = (uint32_t)row*ROWB + ch*16;
        cp_async16(sbase + T1_B + soff, g_B2 + (size_t)(bn+row)*KC + kb + ch*8);
    }
}

__device__ __forceinline__ void ldfrag1(
    uint32_t sbase, uint32_t aoff, uint32_t boff, int k16,
    uint32_t a[2][4], uint32_t b[4][2])
{
    uint32_t kbyte = (uint32_t)k16 * 32;
    uint32_t stA = sbase + T1_A, stB = sbase + T1_B;
    ldsm4(a[0][0], a[0][1], a[0][2], a[0][3], stA + aoff + kbyte);
    ldsm4(a[1][0], a[1][1], a[1][2], a[1][3], stA + aoff + 16*ROWB + kbyte);
    ldsm4(b[0][0], b[0][1], b[1][0], b[1][1], stB + boff + kbyte);
    ldsm4(b[2][0], b[2][1], b[3][0], b[3][1], stB + boff + 16*ROWB + kbyte);
}

__global__ void __launch_bounds__(512, 1) gemm2_kernel(
    const float* __restrict__ resid, float* __restrict__ outp)
{
    extern __shared__ char smem[];
    uint32_t sb = smem_u32(smem);
    int tid = threadIdx.x;
    int wid = tid >> 5, lane = tid & 31;
    int wy = wid >> 2, wx = wid & 3;        // 4x4 warp grid, 32x32 tiles
    int rq = lane >> 2, tq = lane & 3;
    int bm = blockIdx.y * BM;
    int bn = blockIdx.x * BN;
    const int nK = KC / BK;  // 34

    uint32_t aoff = (uint32_t)(wy*32 + (lane & 15))*ROWB + ((lane >> 4) & 1)*16;
    uint32_t boff = (uint32_t)(wx*32 + (lane & 7) + ((lane & 16) >> 1))*ROWB + ((lane & 8) << 1);

    float c[2][4][4] = {};
    uint32_t af[2][2][4], bf[2][4][2];      // double-buffered fragments

    prefetch1(sb + 0*S1_STAGEB, bm, bn, 0,  tid); CP_COMMIT();
    prefetch1(sb + 1*S1_STAGEB, bm, bn, BK, tid); CP_COMMIT();
    CP_WAIT1();
    __syncthreads();
    ldfrag1(sb + 0*S1_STAGEB, aoff, boff, 0, af[0], bf[0]);

    int stage = 0;
    for (int kt = 0; kt < nK; kt++) {
        // Write stage+2: its last old-data reads finished before the previous
        // iteration's __syncthreads (single barrier per iter, below).
        if (kt + 2 < nK) {
            int ps = stage + 2; if (ps >= S1_STAGES) ps -= S1_STAGES;
            prefetch1(sb + ps*S1_STAGEB, bm, bn, (kt+2)*BK, tid);
        }
        CP_COMMIT();

        uint32_t cbase = sb + stage*S1_STAGEB;
        int ns = stage + 1; if (ns >= S1_STAGES) ns = 0;
        uint32_t nbase = sb + ns*S1_STAGEB;

        #pragma unroll
        for (int k16 = 0; k16 < 4; k16++) {
            int cur = k16 & 1, nxt = cur ^ 1;
            if (k16 < 3) {
                ldfrag1(cbase, aoff, boff, k16 + 1, af[nxt], bf[nxt]);
            } else {
                CP_WAIT1();            // stage+1 data complete (own thread)
                __syncthreads();       // ...and visible from all threads
                ldfrag1(nbase, aoff, boff, 0, af[nxt], bf[nxt]);
            }
            #pragma unroll
            for (int i = 0; i < 2; i++)
                #pragma unroll
                for (int j = 0; j < 4; j++)
                    mma16816(c[i][j], af[cur][i], bf[cur][j]);
        }
        stage = ns;
    }

    // Epilogue: residual add
    #pragma unroll
    for (int i = 0; i < 2; i++) {
        int row0 = bm + wy*32 + i*16 + rq;
        #pragma unroll
        for (int j = 0; j < 4; j++) {
            int col = bn + wx*32 + j*8 + tq*2;
            size_t o0 = (size_t)row0 * Hh + col;
            size_t o1 = (size_t)(row0 + 8) * Hh + col;
            float2 r0 = *(const float2*)(resid + o0);
            float2 r1 = *(const float2*)(resid + o1);
            float2 v0 = { r0.x + c[i][j][0], r0.y + c[i][j][1] };
            float2 v1 = { r1.x + c[i][j][2], r1.y + c[i][j][3] };
            *(float2*)(outp + o0) = v0;
            *(float2*)(outp + o1) = v1;
        }
    }
}

// ---------------------------------------------------------------------------
// Host launcher
// ---------------------------------------------------------------------------
extern "C" void kernel_launch(void* const* d_in, const int* in_sizes, int n_in,
                              void* d_out, int out_size) {
    const float* x    = (const float*)d_in[0];
    const float* ln_w = (const float*)d_in[1];
    const float* Wk   = (const float*)d_in[2];
    const float* st   = (const float*)d_in[3];
    const float* emb  = (const float*)d_in[4];
    const float* Wout = (const float*)d_in[5];
    float* out = (float*)d_out;

    cudaFuncSetAttribute(gemms_kernel, cudaFuncAttributeMaxDynamicSharedMemorySize, S3_SMEM);
    cudaFuncSetAttribute(gemm2_kernel, cudaFuncAttributeMaxDynamicSharedMemorySize, S1_SMEM);

    // Launch order keeps gemm2 as the 4th launch (the one ncu samples).
    prep_kernel<<<NB_TR + 128, 256>>>(Wout, Wk, st);
    rmsnorm_kernel<<<Tt, 256>>>(x, ln_w);

    // GEMM-S: sims + argmax + gather -> writes mem into combined cols [0,128)
    gemms_kernel<<<Tt/BM, 256, S3_SMEM>>>(emb);

    // GEMM2: out = x + combined @ Wout^T
    gemm2_kernel<<<dim3(Hh/BN, Tt/BM), 512, S1_SMEM>>>(x, out);
}

// round 15
// speedup vs baseline: 1.4201x; 1.1587x over previous
#include <cuda_runtime.h>
#include <cuda_fp16.h>
#include <cstdint>

// Problem dims (fixed by the dataset)
#define Bb 4
#define Ss 4096
#define Tt (Bb*Ss)     // 16384 tokens
#define Hh 2048
#define Mm 8
#define PKk 32
#define NSn 16
#define Vv 128
#define KC (Vv+Hh)     // 2176

// ---------------------------------------------------------------------------
// Global scratch (static __device__ arrays; allocation-free)
// ---------------------------------------------------------------------------
__device__ __align__(16) __half g_Ahi[(size_t)Tt*KC];   // combined [mem|h] hi fp16
__device__ __align__(16) __half g_Alo[(size_t)Tt*KC];   // combined [mem|h] lo fp16
__device__ __align__(16) __half g_B2 [(size_t)Hh*KC];   // Wout^T fp16 [2048][2176]
__device__ __align__(16) __half g_Shi[(size_t)128*Hh];  // S = Wk^T @ sln, hi [128][2048]
__device__ __align__(16) __half g_Slo[(size_t)128*Hh];  // S lo

__device__ __forceinline__ void split2h(float v, __half& hi, __half& lo) {
    hi = __float2half(v);
    lo = __float2half(v - __half2float(hi));
}

__device__ __forceinline__ uint32_t smem_u32(const void* p) {
    uint32_t a;
    asm("{ .reg .u64 t; cvta.to.shared.u64 t, %1; cvt.u32.u64 %0, t; }" : "=r"(a) : "l"(p));
    return a;
}
__device__ __forceinline__ void cp_async16(uint32_t dst, const void* src) {
    asm volatile("cp.async.cg.shared.global [%0], [%1], 16;" :: "r"(dst), "l"(src));
}
#define CP_COMMIT()  asm volatile("cp.async.commit_group;" ::: "memory")
#define CP_WAIT1()   asm volatile("cp.async.wait_group 1;" ::: "memory")

__device__ __forceinline__ void ldsm4(uint32_t& r0, uint32_t& r1, uint32_t& r2, uint32_t& r3,
                                      uint32_t a) {
    asm volatile("ldmatrix.sync.aligned.m8n8.x4.shared.b16 {%0,%1,%2,%3}, [%4];"
                 : "=r"(r0), "=r"(r1), "=r"(r2), "=r"(r3) : "r"(a));
}

__device__ __forceinline__ void mma16816(float* c, const uint32_t* a, const uint32_t* b) {
    asm volatile(
        "mma.sync.aligned.m16n8k16.row.col.f32.f16.f16.f32 "
        "{%0,%1,%2,%3}, {%4,%5,%6,%7}, {%8,%9}, {%0,%1,%2,%3};"
        : "+f"(c[0]), "+f"(c[1]), "+f"(c[2]), "+f"(c[3])
        : "r"(a[0]), "r"(a[1]), "r"(a[2]), "r"(a[3]), "r"(b[0]), "r"(b[1]));
}

// ---------------------------------------------------------------------------
// Prep kernel (merged): Wout transpose + S computation
// ---------------------------------------------------------------------------
#define NB_TR ((Hh/32) * (KC/32))   // 4352

__global__ void __launch_bounds__(256) prep_kernel(
    const float* __restrict__ W,      // Wout [2176][2048]
    const float* __restrict__ Wk,     // [8][32][2048]
    const float* __restrict__ st)     // slot_tables [8][16][32]
{
    __shared__ float tile[32][33];
    __shared__ float s[PKk];
    int b = blockIdx.x;
    int tid = threadIdx.x;

    if (b < NB_TR) {
        int n0 = (b % (Hh/32)) * 32;
        int k0 = (b / (Hh/32)) * 32;
        int tx = tid & 31, ty = tid >> 5;
        #pragma unroll
        for (int i = 0; i < 32; i += 8)
            tile[ty + i][tx] = W[(size_t)(k0 + ty + i) * Hh + n0 + tx];
        __syncthreads();
        #pragma unroll
        for (int i = 0; i < 32; i += 8) {
            float v = tile[tx][ty + i];
            g_B2[(size_t)(n0 + ty + i) * KC + k0 + tx] = __float2half(v);
        }
    } else {
        int mn = b - NB_TR;                  // 0..127
        int m = mn >> 4;
        if (tid < PKk) {
            float v = st[mn*PKk + tid];
            float ss = v*v;
            #pragma unroll
            for (int o = 16; o > 0; o >>= 1) ss += __shfl_xor_sync(0xffffffffu, ss, o);
            float inv = 1.0f / fmaxf(sqrtf(ss), 1e-12f);
            s[tid] = v * inv;
        }
        __syncthreads();
        const float* wb = Wk + (size_t)m * PKk * Hh;
        for (int h = tid; h < Hh; h += 256) {
            float acc = 0.f;
            #pragma unroll
            for (int k = 0; k < PKk; k++) acc += wb[(size_t)k*Hh + h] * s[k];
            __half hi, lo; split2h(acc, hi, lo);
            g_Shi[(size_t)mn*Hh + h] = hi;
            g_Slo[(size_t)mn*Hh + h] = lo;
        }
    }
}

// ---------------------------------------------------------------------------
// RMSNorm -> hi/lo fp16 split into combined buffer cols [128, 2176)
// ---------------------------------------------------------------------------
__global__ void rmsnorm_kernel(const float* __restrict__ x, const float* __restrict__ w) {
    __shared__ float red[8];
    int t   = blockIdx.x;
    int tid = threadIdx.x;
    const float4* xr = (const float4*)(x + (size_t)t * Hh);
    float4 v0 = xr[tid];
    float4 v1 = xr[tid + 256];
    float ss = v0.x*v0.x + v0.y*v0.y + v0.z*v0.z + v0.w*v0.w
             + v1.x*v1.x + v1.y*v1.y + v1.z*v1.z + v1.w*v1.w;
    int lane = tid & 31, wp = tid >> 5;
    #pragma unroll
    for (int o = 16; o > 0; o >>= 1) ss += __shfl_xor_sync(0xffffffffu, ss, o);
    if (lane == 0) red[wp] = ss;
    __syncthreads();
    if (wp == 0) {
        float v = (lane < 8) ? red[lane] : 0.f;
        #pragma unroll
        for (int o = 4; o > 0; o >>= 1) v += __shfl_xor_sync(0xffffffffu, v, o);
        if (lane == 0) red[0] = v;
    }
    __syncthreads();
    float scale = rsqrtf(red[0] * (1.0f / Hh) + 1e-6f);

    const float4* wr = (const float4*)w;
    float4 w0 = wr[tid], w1 = wr[tid + 256];
    float o0[4] = { v0.x*scale*w0.x, v0.y*scale*w0.y, v0.z*scale*w0.z, v0.w*scale*w0.w };
    float o1[4] = { v1.x*scale*w1.x, v1.y*scale*w1.y, v1.z*scale*w1.z, v1.w*scale*w1.w };

    __half* dh = g_Ahi + (size_t)t * KC + 128;
    __half* dl = g_Alo + (size_t)t * KC + 128;
    #pragma unroll
    for (int j = 0; j < 4; j++) {
        __half hi, lo;
        split2h(o0[j], hi, lo); dh[tid*4 + j] = hi; dl[tid*4 + j] = lo;
        split2h(o1[j], hi, lo); dh[(tid+256)*4 + j] = hi; dl[(tid+256)*4 + j] = lo;
    }
}

// ---------------------------------------------------------------------------
// Shared GEMM tiling constants: BK=64, 3-stage ring
// ---------------------------------------------------------------------------
#define BM 128
#define BN 128
#define BK 64
#define ROWB 144                // 128B data + 16B pad; 8-row ldmatrix hits all 32 banks
#define TILEB (128*ROWB)        // 18432 B per tile

// ===========================================================================
// GEMM-S: sims = h @ S^T, 3-pass fp16 split, fused argmax + emb gather.
// (unchanged from best-known config)
// ===========================================================================
#define S3_STAGES 3
#define S3_STAGEB (4*TILEB)
#define S3_SMEM (S3_STAGES*S3_STAGEB)   // 221184 B
#define T3_AHI 0
#define T3_ALO TILEB
#define T3_BHI (2*TILEB)
#define T3_BLO (3*TILEB)

__device__ __forceinline__ void prefetch3(uint32_t sbase, int bm, int kb, int tid)
{
    const __half* Ah = g_Ahi + 128;
    const __half* Al = g_Alo + 128;
    #pragma unroll
    for (int q = 0; q < 4; q++) {
        int idx = tid + q*256;               // 0..1023
        int row = idx >> 3, ch = idx & 7;
        uint32_t soff = (uint32_t)row*ROWB + ch*16;
        cp_async16(sbase + T3_AHI + soff, Ah + (size_t)(bm+row)*KC + kb + ch*8);
    }
    #pragma unroll
    for (int q = 0; q < 4; q++) {
        int idx = tid + q*256;
        int row = idx >> 3, ch = idx & 7;
        uint32_t soff = (uint32_t)row*ROWB + ch*16;
        cp_async16(sbase + T3_ALO + soff, Al + (size_t)(bm+row)*KC + kb + ch*8);
    }
    #pragma unroll
    for (int q = 0; q < 4; q++) {
        int idx = tid + q*256;
        int row = idx >> 3, ch = idx & 7;
        uint32_t soff = (uint32_t)row*ROWB + ch*16;
        cp_async16(sbase + T3_BHI + soff, g_Shi + (size_t)row*Hh + kb + ch*8);
    }
    #pragma unroll
    for (int q = 0; q < 4; q++) {
        int idx = tid + q*256;
        int row = idx >> 3, ch = idx & 7;
        uint32_t soff = (uint32_t)row*ROWB + ch*16;
        cp_async16(sbase + T3_BLO + soff, g_Slo + (size_t)row*Hh + kb + ch*8);
    }
}

__global__ void __launch_bounds__(256) gemms_kernel(const float* __restrict__ emb) {
    extern __shared__ char smem[];
    __shared__ int idx_s[128][8];
    uint32_t sb = smem_u32(smem);
    int tid = threadIdx.x;
    int wid = tid >> 5, lane = tid & 31;
    int wm = wid >> 2, wn = wid & 3;
    int rq = lane >> 2, tq = lane & 3;
    int bm = blockIdx.x * BM;
    const int nK = Hh / BK;   // 32

    uint32_t aoff = (uint32_t)(wm*64 + (lane & 15))*ROWB + ((lane >> 4) & 1)*16;
    uint32_t boff = (uint32_t)(wn*32 + (lane & 7) + ((lane & 16) >> 1))*ROWB + ((lane & 8) << 1);

    float c[4][4][4] = {};

    prefetch3(sb + 0*S3_STAGEB, bm, 0,  tid); CP_COMMIT();
    prefetch3(sb + 1*S3_STAGEB, bm, BK, tid); CP_COMMIT();

    int stage = 0;
    for (int kt = 0; kt < nK; kt++) {
        CP_WAIT1();
        __syncthreads();
        if (kt + 2 < nK) {
            int ps = stage + 2; if (ps >= S3_STAGES) ps -= S3_STAGES;
            prefetch3(sb + ps*S3_STAGEB, bm, (kt+2)*BK, tid);
        }
        CP_COMMIT();

        uint32_t stAhi = sb + stage*S3_STAGEB + T3_AHI;
        uint32_t stAlo = sb + stage*S3_STAGEB + T3_ALO;
        uint32_t stBhi = sb + stage*S3_STAGEB + T3_BHI;
        uint32_t stBlo = sb + stage*S3_STAGEB + T3_BLO;

        #pragma unroll
        for (int k16 = 0; k16 < 4; k16++) {
            uint32_t kbyte = k16*32;
            uint32_t ah[4][4], al[4][4];
            #pragma unroll
            for (int i = 0; i < 4; i++) {
                ldsm4(ah[i][0], ah[i][1], ah[i][2], ah[i][3], stAhi + aoff + i*16*ROWB + kbyte);
                ldsm4(al[i][0], al[i][1], al[i][2], al[i][3], stAlo + aoff + i*16*ROWB + kbyte);
            }
            uint32_t bh[4][2], bl[4][2];
            ldsm4(bh[0][0], bh[0][1], bh[1][0], bh[1][1], stBhi + boff + kbyte);
            ldsm4(bh[2][0], bh[2][1], bh[3][0], bh[3][1], stBhi + boff + 16*ROWB + kbyte);
            ldsm4(bl[0][0], bl[0][1], bl[1][0], bl[1][1], stBlo + boff + kbyte);
            ldsm4(bl[2][0], bl[2][1], bl[3][0], bl[3][1], stBlo + boff + 16*ROWB + kbyte);
            #pragma unroll
            for (int i = 0; i < 4; i++)
                #pragma unroll
                for (int j = 0; j < 4; j++) {
                    mma16816(c[i][j], ah[i], bh[j]);
                    mma16816(c[i][j], ah[i], bl[j]);
                    mma16816(c[i][j], al[i], bh[j]);
                }
        }
        __syncthreads();
        stage++; if (stage >= S3_STAGES) stage = 0;
    }

    // Fused argmax epilogue: per row, per m-group (16 slots), first-max-wins.
    #pragma unroll
    for (int i = 0; i < 4; i++) {
        #pragma unroll
        for (int half = 0; half < 2; half++) {
            #pragma unroll
            for (int mg = 0; mg < 2; mg++) {
                float bv = c[i][mg*2][half*2+0]; int bs = tq*2;
                float v  = c[i][mg*2][half*2+1];
                if (v > bv) { bv = v; bs = tq*2+1; }
                v = c[i][mg*2+1][half*2+0];
                if (v > bv) { bv = v; bs = 8+tq*2; }
                v = c[i][mg*2+1][half*2+1];
                if (v > bv) { bv = v; bs = 8+tq*2+1; }
                #pragma unroll
                for (int o = 1; o <= 2; o <<= 1) {
                    float ov = __shfl_xor_sync(0xffffffffu, bv, o);
                    int   os = __shfl_xor_sync(0xffffffffu, bs, o);
                    if (ov > bv || (ov == bv && os < bs)) { bv = ov; bs = os; }
                }
                if (tq == 0)
                    idx_s[wm*64 + i*16 + half*8 + rq][2*wn + mg] = bs;
            }
        }
    }
    __syncthreads();

    // Gather + mean + fp16 split into combined cols [0,128)
    {
        int r  = tid >> 1;
        int c0 = (tid & 1) * 64;
        int ids[8];
        #pragma unroll
        for (int g = 0; g < 8; g++) ids[g] = idx_s[r][g];
        __half* dh = g_Ahi + (size_t)(bm + r) * KC + c0;
        __half* dl = g_Alo + (size_t)(bm + r) * KC + c0;
        for (int cc = 0; cc < 64; cc += 4) {
            float4 acc = {0.f, 0.f, 0.f, 0.f};
            #pragma unroll
            for (int g = 0; g < 8; g++) {
                float4 e = *(const float4*)(emb + ids[g]*Vv + c0 + cc);
                acc.x += e.x; acc.y += e.y; acc.z += e.z; acc.w += e.w;
            }
            __half hi, lo;
            split2h(acc.x * 0.125f, hi, lo); dh[cc+0] = hi; dl[cc+0] = lo;
            split2h(acc.y * 0.125f, hi, lo); dh[cc+1] = hi; dl[cc+1] = lo;
            split2h(acc.z * 0.125f, hi, lo); dh[cc+2] = hi; dl[cc+2] = lo;
            split2h(acc.w * 0.125f, hi, lo); dh[cc+3] = hi; dl[cc+3] = lo;
        }
    }
}

// ===========================================================================
// GEMM2: out = x + combined(fp16) @ Wout^T(fp16), single pass.
// 128 threads (4 warps, 2x2 grid, 64x64 warp tiles), BK=64, 3-stage ring,
// cross-barrier fragment double-buffering, 2 CTAs/SM.
// Smem traffic: 128 B/MMA reads (half of 32x32 tiles) -> smem no longer binds.
// ===========================================================================
#define S1_STAGES 3
#define S1_STAGEB (2*TILEB)
#define S1_SMEM (S1_STAGES*S1_STAGEB)   // 110592 B
#define T1_A 0
#define T1_B TILEB

__device__ __forceinline__ void prefetch1(uint32_t sbase, int bm, int bn, int kb, int tid)
{
    #pragma unroll
    for (int q = 0; q < 8; q++) {
        int idx = tid + q*128;               // 0..1023
        int row = idx >> 3, ch = idx & 7;
        uint32_t soff = (uint32_t)row*ROWB + ch*16;
        cp_async16(sbase + T1_A + soff, g_Ahi + (size_t)(bm+row)*KC + kb + ch*8);
    }
    #pragma unroll
    for (int q = 0; q < 8; q++) {
        int idx = tid + q*128;
        int row = idx >> 3, ch = idx & 7;
        uint32_t soff = (uint32_t)row*ROWB + ch*16;
        cp_async16(sbase + T1_B + soff, g_B2 + (size_t)(bn+row)*KC + kb + ch*8);
    }
}

__device__ __forceinline__ void ldfrag1(
    uint32_t sbase, uint32_t aoff, uint32_t boff, int k16,
    uint32_t a[4][4], uint32_t b[8][2])
{
    uint32_t kbyte = (uint32_t)k16 * 32;
    uint32_t stA = sbase + T1_A, stB = sbase + T1_B;
    #pragma unroll
    for (int i = 0; i < 4; i++)
        ldsm4(a[i][0], a[i][1], a[i][2], a[i][3], stA + aoff + i*16*ROWB + kbyte);
    #pragma unroll
    for (int p = 0; p < 4; p++)
        ldsm4(b[2*p][0], b[2*p][1], b[2*p+1][0], b[2*p+1][1],
              stB + boff + p*16*ROWB + kbyte);
}

__global__ void __launch_bounds__(128, 2) gemm2_kernel(
    const float* __restrict__ resid, float* __restrict__ outp)
{
    extern __shared__ char smem[];
    uint32_t sb = smem_u32(smem);
    int tid = threadIdx.x;
    int wid = tid >> 5, lane = tid & 31;
    int wy = wid >> 1, wx = wid & 1;        // 2x2 warp grid, 64x64 tiles
    int rq = lane >> 2, tq = lane & 3;
    int bm = blockIdx.y * BM;
    int bn = blockIdx.x * BN;
    const int nK = KC / BK;  // 34

    uint32_t aoff = (uint32_t)(wy*64 + (lane & 15))*ROWB + ((lane >> 4) & 1)*16;
    uint32_t boff = (uint32_t)(wx*64 + (lane & 7) + ((lane & 16) >> 1))*ROWB + ((lane & 8) << 1);

    float c[4][8][4] = {};                  // 128 accum regs
    uint32_t af[2][4][4], bf[2][8][2];      // double-buffered fragments

    prefetch1(sb + 0*S1_STAGEB, bm, bn, 0,  tid); CP_COMMIT();
    prefetch1(sb + 1*S1_STAGEB, bm, bn, BK, tid); CP_COMMIT();
    CP_WAIT1();
    __syncthreads();
    ldfrag1(sb + 0*S1_STAGEB, aoff, boff, 0, af[0], bf[0]);

    int stage = 0;
    for (int kt = 0; kt < nK; kt++) {
        // Write stage+2: its last old-data reads finished before the previous
        // iteration's __syncthreads (single barrier per iter, below).
        if (kt + 2 < nK) {
            int ps = stage + 2; if (ps >= S1_STAGES) ps -= S1_STAGES;
            prefetch1(sb + ps*S1_STAGEB, bm, bn, (kt+2)*BK, tid);
        }
        CP_COMMIT();

        uint32_t cbase = sb + stage*S1_STAGEB;
        int ns = stage + 1; if (ns >= S1_STAGES) ns = 0;
        uint32_t nbase = sb + ns*S1_STAGEB;

        #pragma unroll
        for (int k16 = 0; k16 < 4; k16++) {
            int cur = k16 & 1, nxt = cur ^ 1;
            if (k16 < 3) {
                ldfrag1(cbase, aoff, boff, k16 + 1, af[nxt], bf[nxt]);
            } else {
                CP_WAIT1();            // stage+1 data complete (own thread)
                __syncthreads();       // ...and visible from all threads
                ldfrag1(nbase, aoff, boff, 0, af[nxt], bf[nxt]);
            }
            #pragma unroll
            for (int i = 0; i < 4; i++)
                #pragma unroll
                for (int j = 0; j < 8; j++)
                    mma16816(c[i][j], af[cur][i], bf[cur][j]);
        }
        stage = ns;
    }

    // Epilogue: residual add
    #pragma unroll
    for (int i = 0; i < 4; i++) {
        int row0 = bm + wy*64 + i*16 + rq;
        #pragma unroll
        for (int j = 0; j < 8; j++) {
            int col = bn + wx*64 + j*8 + tq*2;
            size_t o0 = (size_t)row0 * Hh + col;
            size_t o1 = (size_t)(row0 + 8) * Hh + col;
            float2 r0 = *(const float2*)(resid + o0);
            float2 r1 = *(const float2*)(resid + o1);
            float2 v0 = { r0.x + c[i][j][0], r0.y + c[i][j][1] };
            float2 v1 = { r1.x + c[i][j][2], r1.y + c[i][j][3] };
            *(float2*)(outp + o0) = v0;
            *(float2*)(outp + o1) = v1;
        }
    }
}

// ---------------------------------------------------------------------------
// Host launcher
// ---------------------------------------------------------------------------
extern "C" void kernel_launch(void* const* d_in, const int* in_sizes, int n_in,
                              void* d_out, int out_size) {
    const float* x    = (const float*)d_in[0];
    const float* ln_w = (const float*)d_in[1];
    const float* Wk   = (const float*)d_in[2];
    const float* st   = (const float*)d_in[3];
    const float* emb  = (const float*)d_in[4];
    const float* Wout = (const float*)d_in[5];
    float* out = (float*)d_out;

    cudaFuncSetAttribute(gemms_kernel, cudaFuncAttributeMaxDynamicSharedMemorySize, S3_SMEM);
    cudaFuncSetAttribute(gemm2_kernel, cudaFuncAttributeMaxDynamicSharedMemorySize, S1_SMEM);

    // Launch order keeps gemm2 as the 4th launch (the one ncu samples).
    prep_kernel<<<NB_TR + 128, 256>>>(Wout, Wk, st);
    rmsnorm_kernel<<<Tt, 256>>>(x, ln_w);

    // GEMM-S: sims + argmax + gather -> writes mem into combined cols [0,128)
    gemms_kernel<<<Tt/BM, 256, S3_SMEM>>>(emb);

    // GEMM2: out = x + combined @ Wout^T
    gemm2_kernel<<<dim3(Hh/BN, Tt/BM), 128, S1_SMEM>>>(x, out);
}

// round 16
// speedup vs baseline: 1.4465x; 1.0186x over previous
#include <cuda_runtime.h>
#include <cuda_fp16.h>
#include <cstdint>

// Problem dims (fixed by the dataset)
#define Bb 4
#define Ss 4096
#define Tt (Bb*Ss)     // 16384 tokens
#define Hh 2048
#define Mm 8
#define PKk 32
#define NSn 16
#define Vv 128
#define KC (Vv+Hh)     // 2176

// ---------------------------------------------------------------------------
// Global scratch (static __device__ arrays; allocation-free)
// ---------------------------------------------------------------------------
__device__ __align__(16) __half g_Ahi[(size_t)Tt*KC];   // combined [mem|h] hi fp16
__device__ __align__(16) __half g_Alo[(size_t)Tt*KC];   // combined [mem|h] lo fp16
__device__ __align__(16) __half g_B2 [(size_t)Hh*KC];   // Wout^T fp16 [2048][2176]
__device__ __align__(16) __half g_Shi[(size_t)128*Hh];  // S = Wk^T @ sln, hi [128][2048]
__device__ __align__(16) __half g_Slo[(size_t)128*Hh];  // S lo

__device__ __forceinline__ void split2h(float v, __half& hi, __half& lo) {
    hi = __float2half(v);
    lo = __float2half(v - __half2float(hi));
}

__device__ __forceinline__ uint32_t smem_u32(const void* p) {
    uint32_t a;
    asm("{ .reg .u64 t; cvta.to.shared.u64 t, %1; cvt.u32.u64 %0, t; }" : "=r"(a) : "l"(p));
    return a;
}
__device__ __forceinline__ void cp_async16(uint32_t dst, const void* src) {
    asm volatile("cp.async.cg.shared.global [%0], [%1], 16;" :: "r"(dst), "l"(src));
}
#define CP_COMMIT()  asm volatile("cp.async.commit_group;" ::: "memory")
#define CP_WAIT1()   asm volatile("cp.async.wait_group 1;" ::: "memory")

__device__ __forceinline__ void ldsm4(uint32_t& r0, uint32_t& r1, uint32_t& r2, uint32_t& r3,
                                      uint32_t a) {
    asm volatile("ldmatrix.sync.aligned.m8n8.x4.shared.b16 {%0,%1,%2,%3}, [%4];"
                 : "=r"(r0), "=r"(r1), "=r"(r2), "=r"(r3) : "r"(a));
}

__device__ __forceinline__ void mma16816(float* c, const uint32_t* a, const uint32_t* b) {
    asm volatile(
        "mma.sync.aligned.m16n8k16.row.col.f32.f16.f16.f32 "
        "{%0,%1,%2,%3}, {%4,%5,%6,%7}, {%8,%9}, {%0,%1,%2,%3};"
        : "+f"(c[0]), "+f"(c[1]), "+f"(c[2]), "+f"(c[3])
        : "r"(a[0]), "r"(a[1]), "r"(a[2]), "r"(a[3]), "r"(b[0]), "r"(b[1]));
}

// ---------------------------------------------------------------------------
// Prep kernel (merged): Wout transpose + S computation
// ---------------------------------------------------------------------------
#define NB_TR ((Hh/32) * (KC/32))   // 4352

__global__ void __launch_bounds__(256) prep_kernel(
    const float* __restrict__ W,      // Wout [2176][2048]
    const float* __restrict__ Wk,     // [8][32][2048]
    const float* __restrict__ st)     // slot_tables [8][16][32]
{
    __shared__ float tile[32][33];
    __shared__ float s[PKk];
    int b = blockIdx.x;
    int tid = threadIdx.x;

    if (b < NB_TR) {
        int n0 = (b % (Hh/32)) * 32;
        int k0 = (b / (Hh/32)) * 32;
        int tx = tid & 31, ty = tid >> 5;
        #pragma unroll
        for (int i = 0; i < 32; i += 8)
            tile[ty + i][tx] = W[(size_t)(k0 + ty + i) * Hh + n0 + tx];
        __syncthreads();
        #pragma unroll
        for (int i = 0; i < 32; i += 8) {
            float v = tile[tx][ty + i];
            g_B2[(size_t)(n0 + ty + i) * KC + k0 + tx] = __float2half(v);
        }
    } else {
        int mn = b - NB_TR;                  // 0..127
        int m = mn >> 4;
        if (tid < PKk) {
            float v = st[mn*PKk + tid];
            float ss = v*v;
            #pragma unroll
            for (int o = 16; o > 0; o >>= 1) ss += __shfl_xor_sync(0xffffffffu, ss, o);
            float inv = 1.0f / fmaxf(sqrtf(ss), 1e-12f);
            s[tid] = v * inv;
        }
        __syncthreads();
        const float* wb = Wk + (size_t)m * PKk * Hh;
        for (int h = tid; h < Hh; h += 256) {
            float acc = 0.f;
            #pragma unroll
            for (int k = 0; k < PKk; k++) acc += wb[(size_t)k*Hh + h] * s[k];
            __half hi, lo; split2h(acc, hi, lo);
            g_Shi[(size_t)mn*Hh + h] = hi;
            g_Slo[(size_t)mn*Hh + h] = lo;
        }
    }
}

// ---------------------------------------------------------------------------
// RMSNorm -> hi/lo fp16 split into combined buffer cols [128, 2176)
// ---------------------------------------------------------------------------
__global__ void rmsnorm_kernel(const float* __restrict__ x, const float* __restrict__ w) {
    __shared__ float red[8];
    int t   = blockIdx.x;
    int tid = threadIdx.x;
    const float4* xr = (const float4*)(x + (size_t)t * Hh);
    float4 v0 = xr[tid];
    float4 v1 = xr[tid + 256];
    float ss = v0.x*v0.x + v0.y*v0.y + v0.z*v0.z + v0.w*v0.w
             + v1.x*v1.x + v1.y*v1.y + v1.z*v1.z + v1.w*v1.w;
    int lane = tid & 31, wp = tid >> 5;
    #pragma unroll
    for (int o = 16; o > 0; o >>= 1) ss += __shfl_xor_sync(0xffffffffu, ss, o);
    if (lane == 0) red[wp] = ss;
    __syncthreads();
    if (wp == 0) {
        float v = (lane < 8) ? red[lane] : 0.f;
        #pragma unroll
        for (int o = 4; o > 0; o >>= 1) v += __shfl_xor_sync(0xffffffffu, v, o);
        if (lane == 0) red[0] = v;
    }
    __syncthreads();
    float scale = rsqrtf(red[0] * (1.0f / Hh) + 1e-6f);

    const float4* wr = (const float4*)w;
    float4 w0 = wr[tid], w1 = wr[tid + 256];
    float o0[4] = { v0.x*scale*w0.x, v0.y*scale*w0.y, v0.z*scale*w0.z, v0.w*scale*w0.w };
    float o1[4] = { v1.x*scale*w1.x, v1.y*scale*w1.y, v1.z*scale*w1.z, v1.w*scale*w1.w };

    __half* dh = g_Ahi + (size_t)t * KC + 128;
    __half* dl = g_Alo + (size_t)t * KC + 128;
    #pragma unroll
    for (int j = 0; j < 4; j++) {
        __half hi, lo;
        split2h(o0[j], hi, lo); dh[tid*4 + j] = hi; dl[tid*4 + j] = lo;
        split2h(o1[j], hi, lo); dh[(tid+256)*4 + j] = hi; dl[(tid+256)*4 + j] = lo;
    }
}

// ---------------------------------------------------------------------------
// Shared GEMM tiling constants: BK=64, 3-stage ring
// ---------------------------------------------------------------------------
#define BM 128
#define BN 128
#define BK 64
#define ROWB 144                // 128B data + 16B pad; 8-row ldmatrix hits all 32 banks
#define TILEB (128*ROWB)        // 18432 B per tile

// ===========================================================================
// GEMM-S: sims = h @ S^T, 3-pass fp16 split, fused argmax + emb gather.
// 256 threads (2x4 warps, 64x32 tiles), cross-barrier fragment double-buffering.
// ===========================================================================
#define S3_STAGES 3
#define S3_STAGEB (4*TILEB)
#define S3_SMEM (S3_STAGES*S3_STAGEB)   // 221184 B
#define T3_AHI 0
#define T3_ALO TILEB
#define T3_BHI (2*TILEB)
#define T3_BLO (3*TILEB)

__device__ __forceinline__ void prefetch3(uint32_t sbase, int bm, int kb, int tid)
{
    const __half* Ah = g_Ahi + 128;
    const __half* Al = g_Alo + 128;
    #pragma unroll
    for (int q = 0; q < 4; q++) {
        int idx = tid + q*256;               // 0..1023
        int row = idx >> 3, ch = idx & 7;
        uint32_t soff = (uint32_t)row*ROWB + ch*16;
        cp_async16(sbase + T3_AHI + soff, Ah + (size_t)(bm+row)*KC + kb + ch*8);
    }
    #pragma unroll
    for (int q = 0; q < 4; q++) {
        int idx = tid + q*256;
        int row = idx >> 3, ch = idx & 7;
        uint32_t soff = (uint32_t)row*ROWB + ch*16;
        cp_async16(sbase + T3_ALO + soff, Al + (size_t)(bm+row)*KC + kb + ch*8);
    }
    #pragma unroll
    for (int q = 0; q < 4; q++) {
        int idx = tid + q*256;
        int row = idx >> 3, ch = idx & 7;
        uint32_t soff = (uint32_t)row*ROWB + ch*16;
        cp_async16(sbase + T3_BHI + soff, g_Shi + (size_t)row*Hh + kb + ch*8);
    }
    #pragma unroll
    for (int q = 0; q < 4; q++) {
        int idx = tid + q*256;
        int row = idx >> 3, ch = idx & 7;
        uint32_t soff = (uint32_t)row*ROWB + ch*16;
        cp_async16(sbase + T3_BLO + soff, g_Slo + (size_t)row*Hh + kb + ch*8);
    }
}

__device__ __forceinline__ void ldfrag3(
    uint32_t sbase, uint32_t aoff, uint32_t boff, int k16,
    uint32_t ah[4][4], uint32_t al[4][4], uint32_t bh[4][2], uint32_t bl[4][2])
{
    uint32_t kbyte = (uint32_t)k16 * 32;
    uint32_t stAhi = sbase + T3_AHI, stAlo = sbase + T3_ALO;
    uint32_t stBhi = sbase + T3_BHI, stBlo = sbase + T3_BLO;
    #pragma unroll
    for (int i = 0; i < 4; i++) {
        ldsm4(ah[i][0], ah[i][1], ah[i][2], ah[i][3], stAhi + aoff + i*16*ROWB + kbyte);
        ldsm4(al[i][0], al[i][1], al[i][2], al[i][3], stAlo + aoff + i*16*ROWB + kbyte);
    }
    ldsm4(bh[0][0], bh[0][1], bh[1][0], bh[1][1], stBhi + boff + kbyte);
    ldsm4(bh[2][0], bh[2][1], bh[3][0], bh[3][1], stBhi + boff + 16*ROWB + kbyte);
    ldsm4(bl[0][0], bl[0][1], bl[1][0], bl[1][1], stBlo + boff + kbyte);
    ldsm4(bl[2][0], bl[2][1], bl[3][0], bl[3][1], stBlo + boff + 16*ROWB + kbyte);
}

__global__ void __launch_bounds__(256) gemms_kernel(const float* __restrict__ emb) {
    extern __shared__ char smem[];
    __shared__ int idx_s[128][8];
    uint32_t sb = smem_u32(smem);
    int tid = threadIdx.x;
    int wid = tid >> 5, lane = tid & 31;
    int wm = wid >> 2, wn = wid & 3;
    int rq = lane >> 2, tq = lane & 3;
    int bm = blockIdx.x * BM;
    const int nK = Hh / BK;   // 32

    uint32_t aoff = (uint32_t)(wm*64 + (lane & 15))*ROWB + ((lane >> 4) & 1)*16;
    uint32_t boff = (uint32_t)(wn*32 + (lane & 7) + ((lane & 16) >> 1))*ROWB + ((lane & 8) << 1);

    float c[4][4][4] = {};
    uint32_t ah[2][4][4], al[2][4][4], bh[2][4][2], bl[2][4][2];

    prefetch3(sb + 0*S3_STAGEB, bm, 0,  tid); CP_COMMIT();
    prefetch3(sb + 1*S3_STAGEB, bm, BK, tid); CP_COMMIT();
    CP_WAIT1();
    __syncthreads();
    ldfrag3(sb + 0*S3_STAGEB, aoff, boff, 0, ah[0], al[0], bh[0], bl[0]);

    int stage = 0;
    for (int kt = 0; kt < nK; kt++) {
        if (kt + 2 < nK) {
            int ps = stage + 2; if (ps >= S3_STAGES) ps -= S3_STAGES;
            prefetch3(sb + ps*S3_STAGEB, bm, (kt+2)*BK, tid);
        }
        CP_COMMIT();

        uint32_t cbase = sb + stage*S3_STAGEB;
        int ns = stage + 1; if (ns >= S3_STAGES) ns = 0;
        uint32_t nbase = sb + ns*S3_STAGEB;

        #pragma unroll
        for (int k16 = 0; k16 < 4; k16++) {
            int cur = k16 & 1, nxt = cur ^ 1;
            if (k16 < 3) {
                ldfrag3(cbase, aoff, boff, k16 + 1, ah[nxt], al[nxt], bh[nxt], bl[nxt]);
            } else {
                CP_WAIT1();
                __syncthreads();
                ldfrag3(nbase, aoff, boff, 0, ah[nxt], al[nxt], bh[nxt], bl[nxt]);
            }
            #pragma unroll
            for (int i = 0; i < 4; i++)
                #pragma unroll
                for (int j = 0; j < 4; j++) {
                    mma16816(c[i][j], ah[cur][i], bh[cur][j]);
                    mma16816(c[i][j], ah[cur][i], bl[cur][j]);
                    mma16816(c[i][j], al[cur][i], bh[cur][j]);
                }
        }
        stage = ns;
    }

    // Fused argmax epilogue: per row, per m-group (16 slots), first-max-wins.
    #pragma unroll
    for (int i = 0; i < 4; i++) {
        #pragma unroll
        for (int half = 0; half < 2; half++) {
            #pragma unroll
            for (int mg = 0; mg < 2; mg++) {
                float bv = c[i][mg*2][half*2+0]; int bs = tq*2;
                float v  = c[i][mg*2][half*2+1];
                if (v > bv) { bv = v; bs = tq*2+1; }
                v = c[i][mg*2+1][half*2+0];
                if (v > bv) { bv = v; bs = 8+tq*2; }
                v = c[i][mg*2+1][half*2+1];
                if (v > bv) { bv = v; bs = 8+tq*2+1; }
                #pragma unroll
                for (int o = 1; o <= 2; o <<= 1) {
                    float ov = __shfl_xor_sync(0xffffffffu, bv, o);
                    int   os = __shfl_xor_sync(0xffffffffu, bs, o);
                    if (ov > bv || (ov == bv && os < bs)) { bv = ov; bs = os; }
                }
                if (tq == 0)
                    idx_s[wm*64 + i*16 + half*8 + rq][2*wn + mg] = bs;
            }
        }
    }
    __syncthreads();

    // Gather + mean + fp16 split into combined cols [0,128)
    {
        int r  = tid >> 1;
        int c0 = (tid & 1) * 64;
        int ids[8];
        #pragma unroll
        for (int g = 0; g < 8; g++) ids[g] = idx_s[r][g];
        __half* dh = g_Ahi + (size_t)(bm + r) * KC + c0;
        __half* dl = g_Alo + (size_t)(bm + r) * KC + c0;
        for (int cc = 0; cc < 64; cc += 4) {
            float4 acc = {0.f, 0.f, 0.f, 0.f};
            #pragma unroll
            for (int g = 0; g < 8; g++) {
                float4 e = *(const float4*)(emb + ids[g]*Vv + c0 + cc);
                acc.x += e.x; acc.y += e.y; acc.z += e.z; acc.w += e.w;
            }
            __half hi, lo;
            split2h(acc.x * 0.125f, hi, lo); dh[cc+0] = hi; dl[cc+0] = lo;
            split2h(acc.y * 0.125f, hi, lo); dh[cc+1] = hi; dl[cc+1] = lo;
            split2h(acc.z * 0.125f, hi, lo); dh[cc+2] = hi; dl[cc+2] = lo;
            split2h(acc.w * 0.125f, hi, lo); dh[cc+3] = hi; dl[cc+3] = lo;
        }
    }
}

// ===========================================================================
// GEMM2: out = x + combined(fp16) @ Wout^T(fp16), single pass.
// 128 threads (4 warps, 2x2 grid, 64x64 warp tiles), BK=64, 3-stage ring,
// cross-barrier fragment double-buffering, 2 CTAs/SM. (unchanged from R15)
// ===========================================================================
#define S1_STAGES 3
#define S1_STAGEB (2*TILEB)
#define S1_SMEM (S1_STAGES*S1_STAGEB)   // 110592 B
#define T1_A 0
#define T1_B TILEB

__device__ __forceinline__ void prefetch1(uint32_t sbase, int bm, int bn, int kb, int tid)
{
    #pragma unroll
    for (int q = 0; q < 8; q++) {
        int idx = tid + q*128;               // 0..1023
        int row = idx >> 3, ch = idx & 7;
        uint32_t soff = (uint32_t)row*ROWB + ch*16;
        cp_async16(sbase + T1_A + soff, g_Ahi + (size_t)(bm+row)*KC + kb + ch*8);
    }
    #pragma unroll
    for (int q = 0; q < 8; q++) {
        int idx = tid + q*128;
        int row = idx >> 3, ch = idx & 7;
        uint32_t soff = (uint32_t)row*ROWB + ch*16;
        cp_async16(sbase + T1_B + soff, g_B2 + (size_t)(bn+row)*KC + kb + ch*8);
    }
}

__device__ __forceinline__ void ldfrag1(
    uint32_t sbase, uint32_t aoff, uint32_t boff, int k16,
    uint32_t a[4][4], uint32_t b[8][2])
{
    uint32_t kbyte = (uint32_t)k16 * 32;
    uint32_t stA = sbase + T1_A, stB = sbase + T1_B;
    #pragma unroll
    for (int i = 0; i < 4; i++)
        ldsm4(a[i][0], a[i][1], a[i][2], a[i][3], stA + aoff + i*16*ROWB + kbyte);
    #pragma unroll
    for (int p = 0; p < 4; p++)
        ldsm4(b[2*p][0], b[2*p][1], b[2*p+1][0], b[2*p+1][1],
              stB + boff + p*16*ROWB + kbyte);
}

__global__ void __launch_bounds__(128, 2) gemm2_kernel(
    const float* __restrict__ resid, float* __restrict__ outp)
{
    extern __shared__ char smem[];
    uint32_t sb = smem_u32(smem);
    int tid = threadIdx.x;
    int wid = tid >> 5, lane = tid & 31;
    int wy = wid >> 1, wx = wid & 1;        // 2x2 warp grid, 64x64 tiles
    int rq = lane >> 2, tq = lane & 3;
    int bm = blockIdx.y * BM;
    int bn = blockIdx.x * BN;
    const int nK = KC / BK;  // 34

    uint32_t aoff = (uint32_t)(wy*64 + (lane & 15))*ROWB + ((lane >> 4) & 1)*16;
    uint32_t boff = (uint32_t)(wx*64 + (lane & 7) + ((lane & 16) >> 1))*ROWB + ((lane & 8) << 1);

    float c[4][8][4] = {};                  // 128 accum regs
    uint32_t af[2][4][4], bf[2][8][2];      // double-buffered fragments

    prefetch1(sb + 0*S1_STAGEB, bm, bn, 0,  tid); CP_COMMIT();
    prefetch1(sb + 1*S1_STAGEB, bm, bn, BK, tid); CP_COMMIT();
    CP_WAIT1();
    __syncthreads();
    ldfrag1(sb + 0*S1_STAGEB, aoff, boff, 0, af[0], bf[0]);

    int stage = 0;
    for (int kt = 0; kt < nK; kt++) {
        if (kt + 2 < nK) {
            int ps = stage + 2; if (ps >= S1_STAGES) ps -= S1_STAGES;
            prefetch1(sb + ps*S1_STAGEB, bm, bn, (kt+2)*BK, tid);
        }
        CP_COMMIT();

        uint32_t cbase = sb + stage*S1_STAGEB;
        int ns = stage + 1; if (ns >= S1_STAGES) ns = 0;
        uint32_t nbase = sb + ns*S1_STAGEB;

        #pragma unroll
        for (int k16 = 0; k16 < 4; k16++) {
            int cur = k16 & 1, nxt = cur ^ 1;
            if (k16 < 3) {
                ldfrag1(cbase, aoff, boff, k16 + 1, af[nxt], bf[nxt]);
            } else {
                CP_WAIT1();
                __syncthreads();
                ldfrag1(nbase, aoff, boff, 0, af[nxt], bf[nxt]);
            }
            #pragma unroll
            for (int i = 0; i < 4; i++)
                #pragma unroll
                for (int j = 0; j < 8; j++)
                    mma16816(c[i][j], af[cur][i], bf[cur][j]);
        }
        stage = ns;
    }

    // Epilogue: residual add
    #pragma unroll
    for (int i = 0; i < 4; i++) {
        int row0 = bm + wy*64 + i*16 + rq;
        #pragma unroll
        for (int j = 0; j < 8; j++) {
            int col = bn + wx*64 + j*8 + tq*2;
            size_t o0 = (size_t)row0 * Hh + col;
            size_t o1 = (size_t)(row0 + 8) * Hh + col;
            float2 r0 = *(const float2*)(resid + o0);
            float2 r1 = *(const float2*)(resid + o1);
            float2 v0 = { r0.x + c[i][j][0], r0.y + c[i][j][1] };
            float2 v1 = { r1.x + c[i][j][2], r1.y + c[i][j][3] };
            *(float2*)(outp + o0) = v0;
            *(float2*)(outp + o1) = v1;
        }
    }
}

// ---------------------------------------------------------------------------
// Host launcher
// ---------------------------------------------------------------------------
extern "C" void kernel_launch(void* const* d_in, const int* in_sizes, int n_in,
                              void* d_out, int out_size) {
    const float* x    = (const float*)d_in[0];
    const float* ln_w = (const float*)d_in[1];
    const float* Wk   = (const float*)d_in[2];
    const float* st   = (const float*)d_in[3];
    const float* emb  = (const float*)d_in[4];
    const float* Wout = (const float*)d_in[5];
    float* out = (float*)d_out;

    cudaFuncSetAttribute(gemms_kernel, cudaFuncAttributeMaxDynamicSharedMemorySize, S3_SMEM);
    cudaFuncSetAttribute(gemm2_kernel, cudaFuncAttributeMaxDynamicSharedMemorySize, S1_SMEM);

    // Launch order keeps gemm2 as the 4th launch (the one ncu samples).
    prep_kernel<<<NB_TR + 128, 256>>>(Wout, Wk, st);
    rmsnorm_kernel<<<Tt, 256>>>(x, ln_w);

    // GEMM-S: sims + argmax + gather -> writes mem into combined cols [0,128)
    gemms_kernel<<<Tt/BM, 256, S3_SMEM>>>(emb);

    // GEMM2: out = x + combined @ Wout^T
    gemm2_kernel<<<dim3(Hh/BN, Tt/BM), 128, S1_SMEM>>>(x, out);
}